// round 9
// baseline (speedup 1.0000x reference)
#include <cuda_runtime.h>
#include <cuda_bf16.h>
#include <math.h>
#include <stdint.h>

#define NPTS 8192
#define DIMS 128
#define TILE 128
#define NB   (NPTS / TILE)   // 64
#define NTILES (NB * (NB + 1) / 2)   // 2080

// ---- smem layout (bytes) ----
#define ROW_BYTES 144                  // 64 bf16 = 128B + 16B pad (conflict-free LDSM)
#define ARR_BYTES (128 * ROW_BYTES)    // 18432
#define ARR_AH 0
#define ARR_AM (1 * ARR_BYTES)
#define ARR_BH (2 * ARR_BYTES)
#define ARR_BM (3 * ARR_BYTES)
#define BUF_BYTES (4 * ARR_BYTES)      // 73728
#define OFF_NIX   36864
#define OFF_NJX   (OFF_NIX + 128)
#define OFF_NIY   (OFF_NJX + 128)
#define OFF_NJY   (OFF_NIY + 128)
#define OFF_COLPA (OFF_NJY + 128)      // [4][128]
#define OFF_COLPB (OFF_COLPA + 512)    // [4][128]
#define OFF_ROWPA (OFF_COLPB + 512)    // [2][128]
#define OFF_ROWPB (OFF_ROWPA + 256)    // [2][128]
#define SMEM_FLOATS (OFF_ROWPB + 256)  // 38912
#define SMEM_BYTES  (SMEM_FLOATS * 4)  // 155648

// ---- global scratch ----
__device__ __align__(16) __nv_bfloat16 g_xh[NPTS * DIMS];
__device__ __align__(16) __nv_bfloat16 g_xm[NPTS * DIMS];
__device__ __align__(16) __nv_bfloat16 g_yh[NPTS * DIMS];
__device__ __align__(16) __nv_bfloat16 g_ym[NPTS * DIMS];
__device__ float  g_norm_x[NPTS];
__device__ float  g_norm_y[NPTS];
__device__ double g_rs_a[NPTS];
__device__ double g_rs_b[NPTS];
__device__ double g_S[3];

// ---- helpers ----
__device__ __forceinline__ void mma_bf16(float* d,
                                         const uint32_t* a, uint32_t b0, uint32_t b1) {
    asm volatile(
        "mma.sync.aligned.m16n8k16.row.col.f32.bf16.bf16.f32 "
        "{%0,%1,%2,%3}, {%4,%5,%6,%7}, {%8,%9}, {%0,%1,%2,%3};"
        : "+f"(d[0]), "+f"(d[1]), "+f"(d[2]), "+f"(d[3])
        : "r"(a[0]), "r"(a[1]), "r"(a[2]), "r"(a[3]), "r"(b0), "r"(b1));
}

__device__ __forceinline__ void ldsm4(uint32_t* r, uint32_t addr) {
    asm volatile("ldmatrix.sync.aligned.m8n8.x4.shared.b16 {%0,%1,%2,%3}, [%4];"
        : "=r"(r[0]), "=r"(r[1]), "=r"(r[2]), "=r"(r[3]) : "r"(addr));
}

__device__ __forceinline__ uint32_t smem_u32(const void* p) {
    uint32_t a;
    asm("{ .reg .u64 t; cvta.to.shared.u64 t, %1; cvt.u32.u64 %0, t; }" : "=r"(a) : "l"(p));
    return a;
}
__device__ __forceinline__ void cpa16(uint32_t dst, const void* src) {
    asm volatile("cp.async.ca.shared.global [%0], [%1], 16;" :: "r"(dst), "l"(src));
}
#define CP_COMMIT() asm volatile("cp.async.commit_group;" ::: "memory")
#define CP_WAIT(N)  asm volatile("cp.async.wait_group %0;" :: "n"(N) : "memory")

__device__ __forceinline__ void split_bf16(float v, __nv_bfloat16& h, __nv_bfloat16& m) {
    h = __float2bfloat16_rn(v);
    m = __float2bfloat16_rn(v - __bfloat162float(h));
}

// ---- kernel 1: pre-split x/y into bf16 h/m + norms + zero scratch ----
__global__ __launch_bounds__(256, 4)
void prep_kernel(const float* __restrict__ x, const float* __restrict__ y) {
    const int warp = threadIdx.x >> 5, lane = threadIdx.x & 31;
    const int r = blockIdx.x * 8 + warp;
    if (blockIdx.x == 0 && threadIdx.x < 3) g_S[threadIdx.x] = 0.0;

    const float4 vx = reinterpret_cast<const float4*>(x + (size_t)r * DIMS)[lane];
    const float4 vy = reinterpret_cast<const float4*>(y + (size_t)r * DIMS)[lane];

    __nv_bfloat16 h[4], m[4];
    split_bf16(vx.x, h[0], m[0]); split_bf16(vx.y, h[1], m[1]);
    split_bf16(vx.z, h[2], m[2]); split_bf16(vx.w, h[3], m[3]);
    *reinterpret_cast<uint2*>(g_xh + (size_t)r * DIMS + lane * 4) = *reinterpret_cast<uint2*>(h);
    *reinterpret_cast<uint2*>(g_xm + (size_t)r * DIMS + lane * 4) = *reinterpret_cast<uint2*>(m);
    float sx = vx.x * vx.x + vx.y * vx.y + vx.z * vx.z + vx.w * vx.w;

    split_bf16(vy.x, h[0], m[0]); split_bf16(vy.y, h[1], m[1]);
    split_bf16(vy.z, h[2], m[2]); split_bf16(vy.w, h[3], m[3]);
    *reinterpret_cast<uint2*>(g_yh + (size_t)r * DIMS + lane * 4) = *reinterpret_cast<uint2*>(h);
    *reinterpret_cast<uint2*>(g_ym + (size_t)r * DIMS + lane * 4) = *reinterpret_cast<uint2*>(m);
    float sy = vy.x * vy.x + vy.y * vy.y + vy.z * vy.z + vy.w * vy.w;

    const unsigned FULL = 0xffffffffu;
#pragma unroll
    for (int o = 16; o; o >>= 1) {
        sx += __shfl_xor_sync(FULL, sx, o);
        sy += __shfl_xor_sync(FULL, sy, o);
    }
    if (lane == 0) {
        g_norm_x[r] = sx; g_norm_y[r] = sy;
        g_rs_a[r] = 0.0;  g_rs_b[r] = 0.0;
    }
}

// issue cp.async for chunk n: matrix = n&1 (0=x, 1=y), kc = (n>>1)*64, buf = n&1
__device__ __forceinline__ void issue_chunk_n(uint32_t smb, int n, int I, int J, int tid) {
    const __nv_bfloat16* sh  = (n & 1) ? g_yh : g_xh;
    const __nv_bfloat16* sm2 = (n & 1) ? g_ym : g_xm;
    const int kc = (n >> 1) * 64;
    const uint32_t base = smb + (uint32_t)((n & 1) * BUF_BYTES);
#pragma unroll
    for (int i = 0; i < 4; i++) {
        const int t   = tid + i * 256;
        const int r   = t >> 3;
        const int seg = t & 7;
        const uint32_t d = base + (uint32_t)(r * ROW_BYTES + seg * 16);
        const size_t soI = (size_t)(I + r) * DIMS + kc + seg * 8;
        const size_t soJ = (size_t)(J + r) * DIMS + kc + seg * 8;
        cpa16(d + ARR_AH, sh + soI);
        cpa16(d + ARR_AM, sm2 + soI);
        cpa16(d + ARR_BH, sh + soJ);
        cpa16(d + ARR_BM, sm2 + soJ);
    }
    CP_COMMIT();
}

// 4 k16-steps of bf16x3 MMA; same-acc writes spaced 4 apart (hh x4, hm x4, mh x4)
__device__ __forceinline__ void mma_chunk(uint32_t smb, int buf,
                                          float (*acc)[8][4], int mwarp, int nhalf, int lane) {
    const uint32_t base = smb + (uint32_t)(buf * BUF_BYTES);
    const uint32_t aoff = (uint32_t)((mwarp * 32 + (lane & 15)) * ROW_BYTES + (lane >> 4) * 16);
    const uint32_t boff = (uint32_t)((nhalf * 64 + (lane & 7) + ((lane >> 4) & 1) * 8) * ROW_BYTES
                                     + ((lane >> 3) & 1) * 16);
#pragma unroll
    for (int ks = 0; ks < 4; ks++) {
        uint32_t ah[2][4], am[2][4];
#pragma unroll
        for (int mt = 0; mt < 2; mt++) {
            const uint32_t ao = aoff + (uint32_t)(mt * 16 * ROW_BYTES + ks * 32);
            ldsm4(ah[mt], base + ARR_AH + ao);
            ldsm4(am[mt], base + ARR_AM + ao);
        }
#pragma unroll
        for (int ntp = 0; ntp < 4; ntp++) {
            const uint32_t bo = boff + (uint32_t)(ntp * 16 * ROW_BYTES + ks * 32);
            uint32_t bh[4], bm[4];
            ldsm4(bh, base + ARR_BH + bo);
            ldsm4(bm, base + ARR_BM + bo);
            float* a00 = acc[0][2 * ntp];
            float* a01 = acc[0][2 * ntp + 1];
            float* a10 = acc[1][2 * ntp];
            float* a11 = acc[1][2 * ntp + 1];
            // hh across 4 independent accumulators
            mma_bf16(a00, ah[0], bh[0], bh[1]);
            mma_bf16(a10, ah[1], bh[0], bh[1]);
            mma_bf16(a01, ah[0], bh[2], bh[3]);
            mma_bf16(a11, ah[1], bh[2], bh[3]);
            // hm
            mma_bf16(a00, ah[0], bm[0], bm[1]);
            mma_bf16(a10, ah[1], bm[0], bm[1]);
            mma_bf16(a01, ah[0], bm[2], bm[3]);
            mma_bf16(a11, ah[1], bm[2], bm[3]);
            // mh
            mma_bf16(a00, am[0], bh[0], bh[1]);
            mma_bf16(a10, am[1], bh[0], bh[1]);
            mma_bf16(a01, am[0], bh[2], bh[3]);
            mma_bf16(a11, am[1], bh[2], bh[3]);
        }
    }
}

// ---- kernel 2: fused X/Y bf16x3 HMMA tile sweep (triangular 1D grid) ----
__global__ __launch_bounds__(256, 1)
void dcor_mma_kernel() {
    // decode upper-triangle tile index
    const int t = blockIdx.x;
    int bi = (int)((2.0f * NB + 1.0f
                    - sqrtf((2.0f * NB + 1.0f) * (2.0f * NB + 1.0f) - 8.0f * (float)t)) * 0.5f);
    // fix up float rounding: f(bi) = bi*NB - bi*(bi-1)/2 must satisfy f(bi) <= t < f(bi+1)
    while (bi > 0 && bi * NB - bi * (bi - 1) / 2 > t) bi--;
    while ((bi + 1) * NB - (bi + 1) * bi / 2 <= t) bi++;
    const int bj = bi + (t - (bi * NB - bi * (bi - 1) / 2));

    extern __shared__ float sm[];
    const uint32_t smb = smem_u32(sm);
    float* NIX = sm + OFF_NIX;
    float* NJX = sm + OFF_NJX;
    float* NIY = sm + OFF_NIY;
    float* NJY = sm + OFF_NJY;
    float* COLPA = sm + OFF_COLPA;
    float* COLPB = sm + OFF_COLPB;
    float* ROWPA = sm + OFF_ROWPA;
    float* ROWPB = sm + OFF_ROWPB;

    const int tid = threadIdx.x, warp = tid >> 5, lane = tid & 31;
    const bool diag = (bi == bj);
    const int I = bi * TILE, J = bj * TILE;
    const int mwarp = warp & 3, nhalf = warp >> 2;
    const unsigned FULL = 0xffffffffu;

    issue_chunk_n(smb, 0, I, J, tid);
    issue_chunk_n(smb, 1, I, J, tid);

    if (tid < 128) {
        NIX[tid] = g_norm_x[I + tid]; NJX[tid] = g_norm_x[J + tid];
        NIY[tid] = g_norm_y[I + tid]; NJY[tid] = g_norm_y[J + tid];
    }

    float acc_x[2][8][4], acc_y[2][8][4];
#pragma unroll
    for (int mt = 0; mt < 2; mt++)
#pragma unroll
        for (int nt = 0; nt < 8; nt++)
#pragma unroll
            for (int q = 0; q < 4; q++) { acc_x[mt][nt][q] = 0.f; acc_y[mt][nt][q] = 0.f; }

#pragma unroll
    for (int c = 0; c < 4; c++) {
        if (c < 3) { CP_WAIT(1); } else { CP_WAIT(0); }
        __syncthreads();
        mma_chunk(smb, c & 1, (c & 1) ? acc_y : acc_x, mwarp, nhalf, lane);
        if (c < 2) {
            __syncthreads();
            issue_chunk_n(smb, c + 2, I, J, tid);
        }
    }

    // ---- fused epilogue ----
    // hoist NJ values (depend only on nt)
    float njx[8][2], njy[8][2];
#pragma unroll
    for (int nt = 0; nt < 8; nt++) {
        const int col = nhalf * 64 + nt * 8 + (lane & 3) * 2;
        njx[nt][0] = NJX[col]; njx[nt][1] = NJX[col + 1];
        njy[nt][0] = NJY[col]; njy[nt][1] = NJY[col + 1];
    }

    float ssa = 0.f, ssb = 0.f, sab = 0.f;
    float colpa[8][2], colpb[8][2];
    float rowpa[2][2] = {{0.f, 0.f}, {0.f, 0.f}};
    float rowpb[2][2] = {{0.f, 0.f}, {0.f, 0.f}};
#pragma unroll
    for (int nt = 0; nt < 8; nt++) {
        colpa[nt][0] = 0.f; colpa[nt][1] = 0.f;
        colpb[nt][0] = 0.f; colpb[nt][1] = 0.f;
    }

#pragma unroll
    for (int mt = 0; mt < 2; mt++) {
#pragma unroll
        for (int pr = 0; pr < 2; pr++) {
            const int row = mwarp * 32 + mt * 16 + pr * 8 + (lane >> 2);
            const float nIx = NIX[row];
            const float nIy = NIY[row];
#pragma unroll
            for (int nt = 0; nt < 8; nt++) {
                const int col = nhalf * 64 + nt * 8 + (lane & 3) * 2;
                float gx0 = acc_x[mt][nt][pr * 2 + 0];
                float gx1 = acc_x[mt][nt][pr * 2 + 1];
                float gy0 = acc_y[mt][nt][pr * 2 + 0];
                float gy1 = acc_y[mt][nt][pr * 2 + 1];
                float sqx0 = fmaf(-2.f, gx0, nIx + njx[nt][0]);
                float sqx1 = fmaf(-2.f, gx1, nIx + njx[nt][1]);
                float sqy0 = fmaf(-2.f, gy0, nIy + njy[nt][0]);
                float sqy1 = fmaf(-2.f, gy1, nIy + njy[nt][1]);
                float dx0 = (sqx0 > 0.f) ? sqx0 * rsqrtf(sqx0) : 0.f;
                float dx1 = (sqx1 > 0.f) ? sqx1 * rsqrtf(sqx1) : 0.f;
                float dy0 = (sqy0 > 0.f) ? sqy0 * rsqrtf(sqy0) : 0.f;
                float dy1 = (sqy1 > 0.f) ? sqy1 * rsqrtf(sqy1) : 0.f;
                if (diag) {
                    if (row == col)     { dx0 = 0.f; dy0 = 0.f; }
                    if (row == col + 1) { dx1 = 0.f; dy1 = 0.f; }
                }
                ssa = fmaf(dx0, dx0, ssa); ssa = fmaf(dx1, dx1, ssa);
                ssb = fmaf(dy0, dy0, ssb); ssb = fmaf(dy1, dy1, ssb);
                sab = fmaf(dx0, dy0, sab); sab = fmaf(dx1, dy1, sab);
                rowpa[mt][pr] += dx0 + dx1;
                rowpb[mt][pr] += dy0 + dy1;
                colpa[nt][0] += dx0; colpa[nt][1] += dx1;
                colpb[nt][0] += dy0; colpb[nt][1] += dy1;
            }
        }
    }
    double s_aa = (double)ssa, s_bb = (double)ssb, s_ab = (double)sab;

#pragma unroll
    for (int nt = 0; nt < 8; nt++)
#pragma unroll
        for (int c2 = 0; c2 < 2; c2++) {
            float va = colpa[nt][c2], vb = colpb[nt][c2];
            va += __shfl_down_sync(FULL, va, 16);
            va += __shfl_down_sync(FULL, va, 8);
            va += __shfl_down_sync(FULL, va, 4);
            vb += __shfl_down_sync(FULL, vb, 16);
            vb += __shfl_down_sync(FULL, vb, 8);
            vb += __shfl_down_sync(FULL, vb, 4);
            colpa[nt][c2] = va; colpb[nt][c2] = vb;
        }
    if (lane < 4) {
#pragma unroll
        for (int nt = 0; nt < 8; nt++) {
            const int col = nhalf * 64 + nt * 8 + lane * 2;
            COLPA[mwarp * 128 + col]     = colpa[nt][0];
            COLPA[mwarp * 128 + col + 1] = colpa[nt][1];
            COLPB[mwarp * 128 + col]     = colpb[nt][0];
            COLPB[mwarp * 128 + col + 1] = colpb[nt][1];
        }
    }
#pragma unroll
    for (int mt = 0; mt < 2; mt++)
#pragma unroll
        for (int pr = 0; pr < 2; pr++) {
            float va = rowpa[mt][pr], vb = rowpb[mt][pr];
            va += __shfl_down_sync(FULL, va, 1);
            va += __shfl_down_sync(FULL, va, 2);
            vb += __shfl_down_sync(FULL, vb, 1);
            vb += __shfl_down_sync(FULL, vb, 2);
            rowpa[mt][pr] = va; rowpb[mt][pr] = vb;
        }
    if ((lane & 3) == 0) {
#pragma unroll
        for (int mt = 0; mt < 2; mt++)
#pragma unroll
            for (int pr = 0; pr < 2; pr++) {
                const int row = mwarp * 32 + mt * 16 + pr * 8 + (lane >> 2);
                ROWPA[nhalf * 128 + row] = rowpa[mt][pr];
                ROWPB[nhalf * 128 + row] = rowpb[mt][pr];
            }
    }
    __syncthreads();
    if (tid < 128) {
        float csa = COLPA[tid] + COLPA[128 + tid] + COLPA[256 + tid] + COLPA[384 + tid];
        float csb = COLPB[tid] + COLPB[128 + tid] + COLPB[256 + tid] + COLPB[384 + tid];
        float rsa = ROWPA[tid] + ROWPA[128 + tid];
        float rsb = ROWPB[tid] + ROWPB[128 + tid];
        atomicAdd(&g_rs_a[I + tid], (double)rsa);
        atomicAdd(&g_rs_b[I + tid], (double)rsb);
        if (!diag) {
            atomicAdd(&g_rs_a[J + tid], (double)csa);
            atomicAdd(&g_rs_b[J + tid], (double)csb);
        }
    }

    const double w = diag ? 1.0 : 2.0;
    s_aa *= w; s_bb *= w; s_ab *= w;
#pragma unroll
    for (int o = 16; o; o >>= 1) {
        s_aa += __shfl_down_sync(FULL, s_aa, o);
        s_bb += __shfl_down_sync(FULL, s_bb, o);
        s_ab += __shfl_down_sync(FULL, s_ab, o);
    }
    __shared__ double redS[3][8];
    if (lane == 0) { redS[0][warp] = s_aa; redS[1][warp] = s_bb; redS[2][warp] = s_ab; }
    __syncthreads();
    if (tid == 0) {
        double a = 0, b = 0, c = 0;
#pragma unroll
        for (int k = 0; k < 8; k++) { a += redS[0][k]; b += redS[1][k]; c += redS[2][k]; }
        atomicAdd(&g_S[0], a);
        atomicAdd(&g_S[1], b);
        atomicAdd(&g_S[2], c);
    }
}

// ---- kernel 3: combine + final scalar ----
__global__ void finalize_kernel(float* __restrict__ out) {
    int tid = threadIdx.x;
    double dAB = 0, dAA = 0, dBB = 0, Ta = 0, Tb = 0;
    for (int i = tid; i < NPTS; i += 256) {
        double a = g_rs_a[i], b = g_rs_b[i];
        dAB += a * b; dAA += a * a; dBB += b * b; Ta += a; Tb += b;
    }
    const unsigned FULL = 0xffffffffu;
#pragma unroll
    for (int o = 16; o; o >>= 1) {
        dAB += __shfl_down_sync(FULL, dAB, o);
        dAA += __shfl_down_sync(FULL, dAA, o);
        dBB += __shfl_down_sync(FULL, dBB, o);
        Ta  += __shfl_down_sync(FULL, Ta,  o);
        Tb  += __shfl_down_sync(FULL, Tb,  o);
    }
    __shared__ double red[5][8];
    int wid = tid >> 5, lane = tid & 31;
    if (lane == 0) {
        red[0][wid] = dAB; red[1][wid] = dAA; red[2][wid] = dBB;
        red[3][wid] = Ta;  red[4][wid] = Tb;
    }
    __syncthreads();
    if (tid == 0) {
        double sAB = 0, sAA = 0, sBB = 0, ta = 0, tb = 0;
#pragma unroll
        for (int k = 0; k < 8; k++) {
            sAB += red[0][k]; sAA += red[1][k]; sBB += red[2][k];
            ta  += red[3][k]; tb  += red[4][k];
        }
        const double n = (double)NPTS;
        const double inv_n2 = 1.0 / (n * n);
        double xy = (g_S[2] - (2.0 / n) * sAB + ta * tb * inv_n2) * inv_n2;
        double xx = (g_S[0] - (2.0 / n) * sAA + ta * ta * inv_n2) * inv_n2;
        double yy = (g_S[1] - (2.0 / n) * sBB + tb * tb * inv_n2) * inv_n2;
        xy = fmax(xy, 0.0); xx = fmax(xx, 0.0); yy = fmax(yy, 0.0);
        double dcor = -sqrt(xy) / sqrt(sqrt(xx) * sqrt(yy));
        out[0] = (float)dcor;
    }
}

extern "C" void kernel_launch(void* const* d_in, const int* in_sizes, int n_in,
                              void* d_out, int out_size) {
    (void)in_sizes; (void)n_in; (void)out_size;
    const float* x = (const float*)d_in[0];
    const float* y = (const float*)d_in[1];
    float* out = (float*)d_out;

    cudaFuncSetAttribute(dcor_mma_kernel,
                         cudaFuncAttributeMaxDynamicSharedMemorySize, SMEM_BYTES);

    prep_kernel<<<NPTS / 8, 256>>>(x, y);
    dcor_mma_kernel<<<NTILES, 256, SMEM_BYTES>>>();
    finalize_kernel<<<1, 256>>>(out);
}

// round 12
// speedup vs baseline: 1.0124x; 1.0124x over previous
#include <cuda_runtime.h>
#include <cuda_bf16.h>
#include <math.h>
#include <stdint.h>

#define NPTS 8192
#define DIMS 128
#define TILE 128
#define NB   (NPTS / TILE)   // 64
#define NTILES (NB * (NB + 1) / 2)   // 2080
#define NTHREADS 512

// ---- smem layout (bytes) ----
#define ROW_BYTES 144                  // 64 bf16 = 128B + 16B pad (conflict-free LDSM)
#define ARR_BYTES (128 * ROW_BYTES)    // 18432
#define ARR_AH 0
#define ARR_AM (1 * ARR_BYTES)
#define ARR_BH (2 * ARR_BYTES)
#define ARR_BM (3 * ARR_BYTES)
#define BUF_BYTES (4 * ARR_BYTES)      // 73728
// float-indexed tail arrays after the two buffers (147456 B = 36864 floats)
#define OFF_NIX   36864
#define OFF_NJX   (OFF_NIX + 128)
#define OFF_NIY   (OFF_NJX + 128)
#define OFF_NJY   (OFF_NIY + 128)
#define OFF_COLPA (OFF_NJY + 128)      // [4 mwarp][128]
#define OFF_COLPB (OFF_COLPA + 512)
#define OFF_ROWPA (OFF_COLPB + 512)    // [4 nquad][128]
#define OFF_ROWPB (OFF_ROWPA + 512)
#define SMEM_FLOATS (OFF_ROWPB + 512)  // 39424
#define SMEM_BYTES  (SMEM_FLOATS * 4)  // 157696

// ---- global scratch ----
__device__ __align__(16) __nv_bfloat16 g_xh[NPTS * DIMS];
__device__ __align__(16) __nv_bfloat16 g_xm[NPTS * DIMS];
__device__ __align__(16) __nv_bfloat16 g_yh[NPTS * DIMS];
__device__ __align__(16) __nv_bfloat16 g_ym[NPTS * DIMS];
__device__ float  g_norm_x[NPTS];
__device__ float  g_norm_y[NPTS];
__device__ double g_rs_a[NPTS];
__device__ double g_rs_b[NPTS];
__device__ double g_S[3];

// ---- helpers ----
__device__ __forceinline__ void mma_bf16(float* d,
                                         const uint32_t* a, uint32_t b0, uint32_t b1) {
    asm volatile(
        "mma.sync.aligned.m16n8k16.row.col.f32.bf16.bf16.f32 "
        "{%0,%1,%2,%3}, {%4,%5,%6,%7}, {%8,%9}, {%0,%1,%2,%3};"
        : "+f"(d[0]), "+f"(d[1]), "+f"(d[2]), "+f"(d[3])
        : "r"(a[0]), "r"(a[1]), "r"(a[2]), "r"(a[3]), "r"(b0), "r"(b1));
}

__device__ __forceinline__ void ldsm4(uint32_t* r, uint32_t addr) {
    asm volatile("ldmatrix.sync.aligned.m8n8.x4.shared.b16 {%0,%1,%2,%3}, [%4];"
        : "=r"(r[0]), "=r"(r[1]), "=r"(r[2]), "=r"(r[3]) : "r"(addr));
}

__device__ __forceinline__ uint32_t smem_u32(const void* p) {
    uint32_t a;
    asm("{ .reg .u64 t; cvta.to.shared.u64 t, %1; cvt.u32.u64 %0, t; }" : "=r"(a) : "l"(p));
    return a;
}
__device__ __forceinline__ void cpa16(uint32_t dst, const void* src) {
    asm volatile("cp.async.ca.shared.global [%0], [%1], 16;" :: "r"(dst), "l"(src));
}
#define CP_COMMIT() asm volatile("cp.async.commit_group;" ::: "memory")
#define CP_WAIT(N)  asm volatile("cp.async.wait_group %0;" :: "n"(N) : "memory")

__device__ __forceinline__ void split_bf16(float v, __nv_bfloat16& h, __nv_bfloat16& m) {
    h = __float2bfloat16_rn(v);
    m = __float2bfloat16_rn(v - __bfloat162float(h));
}

// ---- kernel 1: pre-split x/y into bf16 h/m + norms + zero scratch ----
__global__ __launch_bounds__(256, 4)
void prep_kernel(const float* __restrict__ x, const float* __restrict__ y) {
    const int warp = threadIdx.x >> 5, lane = threadIdx.x & 31;
    const int r = blockIdx.x * 8 + warp;
    if (blockIdx.x == 0 && threadIdx.x < 3) g_S[threadIdx.x] = 0.0;

    const float4 vx = reinterpret_cast<const float4*>(x + (size_t)r * DIMS)[lane];
    const float4 vy = reinterpret_cast<const float4*>(y + (size_t)r * DIMS)[lane];

    __nv_bfloat16 h[4], m[4];
    split_bf16(vx.x, h[0], m[0]); split_bf16(vx.y, h[1], m[1]);
    split_bf16(vx.z, h[2], m[2]); split_bf16(vx.w, h[3], m[3]);
    *reinterpret_cast<uint2*>(g_xh + (size_t)r * DIMS + lane * 4) = *reinterpret_cast<uint2*>(h);
    *reinterpret_cast<uint2*>(g_xm + (size_t)r * DIMS + lane * 4) = *reinterpret_cast<uint2*>(m);
    float sx = vx.x * vx.x + vx.y * vx.y + vx.z * vx.z + vx.w * vx.w;

    split_bf16(vy.x, h[0], m[0]); split_bf16(vy.y, h[1], m[1]);
    split_bf16(vy.z, h[2], m[2]); split_bf16(vy.w, h[3], m[3]);
    *reinterpret_cast<uint2*>(g_yh + (size_t)r * DIMS + lane * 4) = *reinterpret_cast<uint2*>(h);
    *reinterpret_cast<uint2*>(g_ym + (size_t)r * DIMS + lane * 4) = *reinterpret_cast<uint2*>(m);
    float sy = vy.x * vy.x + vy.y * vy.y + vy.z * vy.z + vy.w * vy.w;

    const unsigned FULL = 0xffffffffu;
#pragma unroll
    for (int o = 16; o; o >>= 1) {
        sx += __shfl_xor_sync(FULL, sx, o);
        sy += __shfl_xor_sync(FULL, sy, o);
    }
    if (lane == 0) {
        g_norm_x[r] = sx; g_norm_y[r] = sy;
        g_rs_a[r] = 0.0;  g_rs_b[r] = 0.0;
    }
}

// issue cp.async for chunk n: matrix = n&1 (0=x, 1=y), kc = (n>>1)*64, buf = n&1
__device__ __forceinline__ void issue_chunk_n(uint32_t smb, int n, int I, int J, int tid) {
    const __nv_bfloat16* sh  = (n & 1) ? g_yh : g_xh;
    const __nv_bfloat16* sm2 = (n & 1) ? g_ym : g_xm;
    const int kc = (n >> 1) * 64;
    const uint32_t base = smb + (uint32_t)((n & 1) * BUF_BYTES);
#pragma unroll
    for (int i = 0; i < 2; i++) {           // 128 rows * 8 segs / 512 threads
        const int t   = tid + i * NTHREADS;
        const int r   = t >> 3;
        const int seg = t & 7;
        const uint32_t d = base + (uint32_t)(r * ROW_BYTES + seg * 16);
        const size_t soI = (size_t)(I + r) * DIMS + kc + seg * 8;
        const size_t soJ = (size_t)(J + r) * DIMS + kc + seg * 8;
        cpa16(d + ARR_AH, sh + soI);
        cpa16(d + ARR_AM, sm2 + soI);
        cpa16(d + ARR_BH, sh + soJ);
        cpa16(d + ARR_BM, sm2 + soJ);
    }
    CP_COMMIT();
}

// 4 k16-steps of bf16x3 MMA over one 64-k chunk; warp sub-tile 32x32
__device__ __forceinline__ void mma_chunk(uint32_t smb, int buf,
                                          float (*acc)[4][4], int mwarp, int nquad, int lane) {
    const uint32_t base = smb + (uint32_t)(buf * BUF_BYTES);
    const uint32_t aoff = (uint32_t)((mwarp * 32 + (lane & 15)) * ROW_BYTES + (lane >> 4) * 16);
    const uint32_t boff = (uint32_t)((nquad * 32 + (lane & 7) + ((lane >> 4) & 1) * 8) * ROW_BYTES
                                     + ((lane >> 3) & 1) * 16);
#pragma unroll
    for (int ks = 0; ks < 4; ks++) {
        uint32_t ah[2][4], am[2][4];
#pragma unroll
        for (int mt = 0; mt < 2; mt++) {
            const uint32_t ao = aoff + (uint32_t)(mt * 16 * ROW_BYTES + ks * 32);
            ldsm4(ah[mt], base + ARR_AH + ao);
            ldsm4(am[mt], base + ARR_AM + ao);
        }
#pragma unroll
        for (int ntp = 0; ntp < 2; ntp++) {
            const uint32_t bo = boff + (uint32_t)(ntp * 16 * ROW_BYTES + ks * 32);
            uint32_t bh[4], bm[4];
            ldsm4(bh, base + ARR_BH + bo);
            ldsm4(bm, base + ARR_BM + bo);
            float* a00 = acc[0][2 * ntp];
            float* a01 = acc[0][2 * ntp + 1];
            float* a10 = acc[1][2 * ntp];
            float* a11 = acc[1][2 * ntp + 1];
            // hh across 4 independent accumulators, then hm, then mh
            mma_bf16(a00, ah[0], bh[0], bh[1]);
            mma_bf16(a10, ah[1], bh[0], bh[1]);
            mma_bf16(a01, ah[0], bh[2], bh[3]);
            mma_bf16(a11, ah[1], bh[2], bh[3]);
            mma_bf16(a00, ah[0], bm[0], bm[1]);
            mma_bf16(a10, ah[1], bm[0], bm[1]);
            mma_bf16(a01, ah[0], bm[2], bm[3]);
            mma_bf16(a11, ah[1], bm[2], bm[3]);
            mma_bf16(a00, am[0], bh[0], bh[1]);
            mma_bf16(a10, am[1], bh[0], bh[1]);
            mma_bf16(a01, am[0], bh[2], bh[3]);
            mma_bf16(a11, am[1], bh[2], bh[3]);
        }
    }
}

// ---- kernel 2: fused X/Y bf16x3 HMMA tile sweep, 16 warps / 512 threads ----
__global__ __launch_bounds__(NTHREADS, 1)
void dcor_mma_kernel() {
    // decode upper-triangle tile index
    const int t = blockIdx.x;
    int bi = (int)((2.0f * NB + 1.0f
                    - sqrtf((2.0f * NB + 1.0f) * (2.0f * NB + 1.0f) - 8.0f * (float)t)) * 0.5f);
    while (bi > 0 && bi * NB - bi * (bi - 1) / 2 > t) bi--;
    while ((bi + 1) * NB - (bi + 1) * bi / 2 <= t) bi++;
    const int bj = bi + (t - (bi * NB - bi * (bi - 1) / 2));

    extern __shared__ float sm[];
    const uint32_t smb = smem_u32(sm);
    float* NIX = sm + OFF_NIX;
    float* NJX = sm + OFF_NJX;
    float* NIY = sm + OFF_NIY;
    float* NJY = sm + OFF_NJY;
    float* COLPA = sm + OFF_COLPA;
    float* COLPB = sm + OFF_COLPB;
    float* ROWPA = sm + OFF_ROWPA;
    float* ROWPB = sm + OFF_ROWPB;

    const int tid = threadIdx.x, warp = tid >> 5, lane = tid & 31;
    const bool diag = (bi == bj);
    const int I = bi * TILE, J = bj * TILE;
    const int mwarp = warp & 3;      // row quarter (32 rows)
    const int nquad = warp >> 2;     // col quarter (32 cols)
    const unsigned FULL = 0xffffffffu;

    issue_chunk_n(smb, 0, I, J, tid);
    issue_chunk_n(smb, 1, I, J, tid);

    if (tid < 128) {
        NIX[tid] = g_norm_x[I + tid]; NJX[tid] = g_norm_x[J + tid];
        NIY[tid] = g_norm_y[I + tid]; NJY[tid] = g_norm_y[J + tid];
    }

    float acc_x[2][4][4], acc_y[2][4][4];
#pragma unroll
    for (int mt = 0; mt < 2; mt++)
#pragma unroll
        for (int nt = 0; nt < 4; nt++)
#pragma unroll
            for (int q = 0; q < 4; q++) { acc_x[mt][nt][q] = 0.f; acc_y[mt][nt][q] = 0.f; }

#pragma unroll
    for (int c = 0; c < 4; c++) {
        if (c < 3) { CP_WAIT(1); } else { CP_WAIT(0); }
        __syncthreads();
        mma_chunk(smb, c & 1, (c & 1) ? acc_y : acc_x, mwarp, nquad, lane);
        if (c < 2) {
            __syncthreads();
            issue_chunk_n(smb, c + 2, I, J, tid);
        }
    }

    // ---- fused epilogue ----
    float njx[4][2], njy[4][2];
#pragma unroll
    for (int nt = 0; nt < 4; nt++) {
        const int col = nquad * 32 + nt * 8 + (lane & 3) * 2;
        njx[nt][0] = NJX[col]; njx[nt][1] = NJX[col + 1];
        njy[nt][0] = NJY[col]; njy[nt][1] = NJY[col + 1];
    }

    float ssa = 0.f, ssb = 0.f, sab = 0.f;
    float colpa[4][2], colpb[4][2];
    float rowpa[2][2] = {{0.f, 0.f}, {0.f, 0.f}};
    float rowpb[2][2] = {{0.f, 0.f}, {0.f, 0.f}};
#pragma unroll
    for (int nt = 0; nt < 4; nt++) {
        colpa[nt][0] = 0.f; colpa[nt][1] = 0.f;
        colpb[nt][0] = 0.f; colpb[nt][1] = 0.f;
    }

#pragma unroll
    for (int mt = 0; mt < 2; mt++) {
#pragma unroll
        for (int pr = 0; pr < 2; pr++) {
            const int row = mwarp * 32 + mt * 16 + pr * 8 + (lane >> 2);
            const float nIx = NIX[row];
            const float nIy = NIY[row];
#pragma unroll
            for (int nt = 0; nt < 4; nt++) {
                const int col = nquad * 32 + nt * 8 + (lane & 3) * 2;
                float gx0 = acc_x[mt][nt][pr * 2 + 0];
                float gx1 = acc_x[mt][nt][pr * 2 + 1];
                float gy0 = acc_y[mt][nt][pr * 2 + 0];
                float gy1 = acc_y[mt][nt][pr * 2 + 1];
                float sqx0 = fmaf(-2.f, gx0, nIx + njx[nt][0]);
                float sqx1 = fmaf(-2.f, gx1, nIx + njx[nt][1]);
                float sqy0 = fmaf(-2.f, gy0, nIy + njy[nt][0]);
                float sqy1 = fmaf(-2.f, gy1, nIy + njy[nt][1]);
                float dx0 = (sqx0 > 0.f) ? sqx0 * rsqrtf(sqx0) : 0.f;
                float dx1 = (sqx1 > 0.f) ? sqx1 * rsqrtf(sqx1) : 0.f;
                float dy0 = (sqy0 > 0.f) ? sqy0 * rsqrtf(sqy0) : 0.f;
                float dy1 = (sqy1 > 0.f) ? sqy1 * rsqrtf(sqy1) : 0.f;
                if (diag) {
                    if (row == col)     { dx0 = 0.f; dy0 = 0.f; }
                    if (row == col + 1) { dx1 = 0.f; dy1 = 0.f; }
                }
                ssa = fmaf(dx0, dx0, ssa); ssa = fmaf(dx1, dx1, ssa);
                ssb = fmaf(dy0, dy0, ssb); ssb = fmaf(dy1, dy1, ssb);
                sab = fmaf(dx0, dy0, sab); sab = fmaf(dx1, dy1, sab);
                rowpa[mt][pr] += dx0 + dx1;
                rowpb[mt][pr] += dy0 + dy1;
                colpa[nt][0] += dx0; colpa[nt][1] += dx1;
                colpb[nt][0] += dy0; colpb[nt][1] += dy1;
            }
        }
    }
    double s_aa = (double)ssa, s_bb = (double)ssb, s_ab = (double)sab;

    // col sums: reduce over the 8 row-lanes
#pragma unroll
    for (int nt = 0; nt < 4; nt++)
#pragma unroll
        for (int c2 = 0; c2 < 2; c2++) {
            float va = colpa[nt][c2], vb = colpb[nt][c2];
            va += __shfl_down_sync(FULL, va, 16);
            va += __shfl_down_sync(FULL, va, 8);
            va += __shfl_down_sync(FULL, va, 4);
            vb += __shfl_down_sync(FULL, vb, 16);
            vb += __shfl_down_sync(FULL, vb, 8);
            vb += __shfl_down_sync(FULL, vb, 4);
            colpa[nt][c2] = va; colpb[nt][c2] = vb;
        }
    if (lane < 4) {
#pragma unroll
        for (int nt = 0; nt < 4; nt++) {
            const int col = nquad * 32 + nt * 8 + lane * 2;
            COLPA[mwarp * 128 + col]     = colpa[nt][0];
            COLPA[mwarp * 128 + col + 1] = colpa[nt][1];
            COLPB[mwarp * 128 + col]     = colpb[nt][0];
            COLPB[mwarp * 128 + col + 1] = colpb[nt][1];
        }
    }
    // row sums: reduce over the 4 col-lanes
#pragma unroll
    for (int mt = 0; mt < 2; mt++)
#pragma unroll
        for (int pr = 0; pr < 2; pr++) {
            float va = rowpa[mt][pr], vb = rowpb[mt][pr];
            va += __shfl_down_sync(FULL, va, 1);
            va += __shfl_down_sync(FULL, va, 2);
            rowpa[mt][pr] = va;
            vb += __shfl_down_sync(FULL, vb, 1);
            vb += __shfl_down_sync(FULL, vb, 2);
            rowpb[mt][pr] = vb;
        }
    if ((lane & 3) == 0) {
#pragma unroll
        for (int mt = 0; mt < 2; mt++)
#pragma unroll
            for (int pr = 0; pr < 2; pr++) {
                const int row = mwarp * 32 + mt * 16 + pr * 8 + (lane >> 2);
                ROWPA[nquad * 128 + row] = rowpa[mt][pr];
                ROWPB[nquad * 128 + row] = rowpb[mt][pr];
            }
    }
    __syncthreads();
    if (tid < 128) {
        float csa = COLPA[tid] + COLPA[128 + tid] + COLPA[256 + tid] + COLPA[384 + tid];
        float csb = COLPB[tid] + COLPB[128 + tid] + COLPB[256 + tid] + COLPB[384 + tid];
        float rsa = ROWPA[tid] + ROWPA[128 + tid] + ROWPA[256 + tid] + ROWPA[384 + tid];
        float rsb = ROWPB[tid] + ROWPB[128 + tid] + ROWPB[256 + tid] + ROWPB[384 + tid];
        atomicAdd(&g_rs_a[I + tid], (double)rsa);
        atomicAdd(&g_rs_b[I + tid], (double)rsb);
        if (!diag) {
            atomicAdd(&g_rs_a[J + tid], (double)csa);
            atomicAdd(&g_rs_b[J + tid], (double)csb);
        }
    }

    // ---- block scalar reduction ----
    const double w = diag ? 1.0 : 2.0;
    s_aa *= w; s_bb *= w; s_ab *= w;
#pragma unroll
    for (int o = 16; o; o >>= 1) {
        s_aa += __shfl_down_sync(FULL, s_aa, o);
        s_bb += __shfl_down_sync(FULL, s_bb, o);
        s_ab += __shfl_down_sync(FULL, s_ab, o);
    }
    __shared__ double redS[3][16];
    if (lane == 0) { redS[0][warp] = s_aa; redS[1][warp] = s_bb; redS[2][warp] = s_ab; }
    __syncthreads();
    if (tid == 0) {
        double a = 0, b = 0, c = 0;
#pragma unroll
        for (int k = 0; k < 16; k++) { a += redS[0][k]; b += redS[1][k]; c += redS[2][k]; }
        atomicAdd(&g_S[0], a);
        atomicAdd(&g_S[1], b);
        atomicAdd(&g_S[2], c);
    }
}

// ---- kernel 3: combine + final scalar ----
__global__ void finalize_kernel(float* __restrict__ out) {
    int tid = threadIdx.x;
    double dAB = 0, dAA = 0, dBB = 0, Ta = 0, Tb = 0;
    for (int i = tid; i < NPTS; i += 256) {
        double a = g_rs_a[i], b = g_rs_b[i];
        dAB += a * b; dAA += a * a; dBB += b * b; Ta += a; Tb += b;
    }
    const unsigned FULL = 0xffffffffu;
#pragma unroll
    for (int o = 16; o; o >>= 1) {
        dAB += __shfl_down_sync(FULL, dAB, o);
        dAA += __shfl_down_sync(FULL, dAA, o);
        dBB += __shfl_down_sync(FULL, dBB, o);
        Ta  += __shfl_down_sync(FULL, Ta,  o);
        Tb  += __shfl_down_sync(FULL, Tb,  o);
    }
    __shared__ double red[5][8];
    int wid = tid >> 5, lane = tid & 31;
    if (lane == 0) {
        red[0][wid] = dAB; red[1][wid] = dAA; red[2][wid] = dBB;
        red[3][wid] = Ta;  red[4][wid] = Tb;
    }
    __syncthreads();
    if (tid == 0) {
        double sAB = 0, sAA = 0, sBB = 0, ta = 0, tb = 0;
#pragma unroll
        for (int k = 0; k < 8; k++) {
            sAB += red[0][k]; sAA += red[1][k]; sBB += red[2][k];
            ta  += red[3][k]; tb  += red[4][k];
        }
        const double n = (double)NPTS;
        const double inv_n2 = 1.0 / (n * n);
        double xy = (g_S[2] - (2.0 / n) * sAB + ta * tb * inv_n2) * inv_n2;
        double xx = (g_S[0] - (2.0 / n) * sAA + ta * ta * inv_n2) * inv_n2;
        double yy = (g_S[1] - (2.0 / n) * sBB + tb * tb * inv_n2) * inv_n2;
        xy = fmax(xy, 0.0); xx = fmax(xx, 0.0); yy = fmax(yy, 0.0);
        double dcor = -sqrt(xy) / sqrt(sqrt(xx) * sqrt(yy));
        out[0] = (float)dcor;
    }
}

extern "C" void kernel_launch(void* const* d_in, const int* in_sizes, int n_in,
                              void* d_out, int out_size) {
    (void)in_sizes; (void)n_in; (void)out_size;
    const float* x = (const float*)d_in[0];
    const float* y = (const float*)d_in[1];
    float* out = (float*)d_out;

    cudaFuncSetAttribute(dcor_mma_kernel,
                         cudaFuncAttributeMaxDynamicSharedMemorySize, SMEM_BYTES);

    prep_kernel<<<NPTS / 8, 256>>>(x, y);
    dcor_mma_kernel<<<NTILES, NTHREADS, SMEM_BYTES>>>();
    finalize_kernel<<<1, 256>>>(out);
}

// round 13
// speedup vs baseline: 1.6865x; 1.6658x over previous
#include <cuda_runtime.h>
#include <cuda_fp16.h>
#include <math.h>
#include <stdint.h>

#define NPTS 8192
#define DIMS 128
#define TILE 128
#define NB   (NPTS / TILE)   // 64
#define NTILES (NB * (NB + 1) / 2)   // 2080

// ---- smem layout (bytes) ----
#define ROW_BYTES 272                  // 128 fp16 = 256B + 16B pad (conflict-free LDSM)
#define ARR_BYTES (128 * ROW_BYTES)    // 34816
#define ARR_A 0
#define ARR_B ARR_BYTES
#define BUF_BYTES (2 * ARR_BYTES)      // 69632
// float-indexed tail after the two buffers (139264 B = 34816 floats)
#define OFF_NIX   34816
#define OFF_NJX   (OFF_NIX + 128)
#define OFF_NIY   (OFF_NJX + 128)
#define OFF_NJY   (OFF_NIY + 128)
#define OFF_COLPA (OFF_NJY + 128)      // [4 mwarp][128]
#define OFF_COLPB (OFF_COLPA + 512)
#define OFF_ROWPA (OFF_COLPB + 512)    // [2 nhalf][128]
#define OFF_ROWPB (OFF_ROWPA + 256)
#define SMEM_FLOATS (OFF_ROWPB + 256)  // 36864
#define SMEM_BYTES  (SMEM_FLOATS * 4)  // 147456

// ---- global scratch ----
__device__ __align__(16) __half g_x16[NPTS * DIMS];
__device__ __align__(16) __half g_y16[NPTS * DIMS];
__device__ float  g_norm_x[NPTS];
__device__ float  g_norm_y[NPTS];
__device__ double g_rs_a[NPTS];
__device__ double g_rs_b[NPTS];
__device__ double g_S[3];

// ---- helpers ----
__device__ __forceinline__ void mma_f16(float* d,
                                        const uint32_t* a, uint32_t b0, uint32_t b1) {
    asm volatile(
        "mma.sync.aligned.m16n8k16.row.col.f32.f16.f16.f32 "
        "{%0,%1,%2,%3}, {%4,%5,%6,%7}, {%8,%9}, {%0,%1,%2,%3};"
        : "+f"(d[0]), "+f"(d[1]), "+f"(d[2]), "+f"(d[3])
        : "r"(a[0]), "r"(a[1]), "r"(a[2]), "r"(a[3]), "r"(b0), "r"(b1));
}

__device__ __forceinline__ void ldsm4(uint32_t* r, uint32_t addr) {
    asm volatile("ldmatrix.sync.aligned.m8n8.x4.shared.b16 {%0,%1,%2,%3}, [%4];"
        : "=r"(r[0]), "=r"(r[1]), "=r"(r[2]), "=r"(r[3]) : "r"(addr));
}

__device__ __forceinline__ uint32_t smem_u32(const void* p) {
    uint32_t a;
    asm("{ .reg .u64 t; cvta.to.shared.u64 t, %1; cvt.u32.u64 %0, t; }" : "=r"(a) : "l"(p));
    return a;
}
__device__ __forceinline__ void cpa16(uint32_t dst, const void* src) {
    asm volatile("cp.async.ca.shared.global [%0], [%1], 16;" :: "r"(dst), "l"(src));
}
#define CP_COMMIT() asm volatile("cp.async.commit_group;" ::: "memory")
#define CP_WAIT(N)  asm volatile("cp.async.wait_group %0;" :: "n"(N) : "memory")

// ---- kernel 1: round x/y to fp16 + norms OF THE ROUNDED VALUES + zero scratch ----
__global__ __launch_bounds__(256, 4)
void prep_kernel(const float* __restrict__ x, const float* __restrict__ y) {
    const int warp = threadIdx.x >> 5, lane = threadIdx.x & 31;
    const int r = blockIdx.x * 8 + warp;
    if (blockIdx.x == 0 && threadIdx.x < 3) g_S[threadIdx.x] = 0.0;

    const float4 vx = reinterpret_cast<const float4*>(x + (size_t)r * DIMS)[lane];
    const float4 vy = reinterpret_cast<const float4*>(y + (size_t)r * DIMS)[lane];

    __half hx[4], hy[4];
    hx[0] = __float2half_rn(vx.x); hx[1] = __float2half_rn(vx.y);
    hx[2] = __float2half_rn(vx.z); hx[3] = __float2half_rn(vx.w);
    hy[0] = __float2half_rn(vy.x); hy[1] = __float2half_rn(vy.y);
    hy[2] = __float2half_rn(vy.z); hy[3] = __float2half_rn(vy.w);
    *reinterpret_cast<uint2*>(g_x16 + (size_t)r * DIMS + lane * 4) = *reinterpret_cast<uint2*>(hx);
    *reinterpret_cast<uint2*>(g_y16 + (size_t)r * DIMS + lane * 4) = *reinterpret_cast<uint2*>(hy);

    float sx = 0.f, sy = 0.f;
#pragma unroll
    for (int q = 0; q < 4; q++) {
        float fx = __half2float(hx[q]), fy = __half2float(hy[q]);
        sx = fmaf(fx, fx, sx);
        sy = fmaf(fy, fy, sy);
    }
    const unsigned FULL = 0xffffffffu;
#pragma unroll
    for (int o = 16; o; o >>= 1) {
        sx += __shfl_xor_sync(FULL, sx, o);
        sy += __shfl_xor_sync(FULL, sy, o);
    }
    if (lane == 0) {
        g_norm_x[r] = sx; g_norm_y[r] = sy;
        g_rs_a[r] = 0.0;  g_rs_b[r] = 0.0;
    }
}

// issue cp.async for chunk n (n=0: x -> buf0, n=1: y -> buf1), full k=128
__device__ __forceinline__ void issue_chunk_n(uint32_t smb, int n, int I, int J, int tid) {
    const __half* src = n ? g_y16 : g_x16;
    const uint32_t base = smb + (uint32_t)(n * BUF_BYTES);
#pragma unroll
    for (int i = 0; i < 8; i++) {           // 128 rows * 16 segs / 256 threads
        const int t   = tid + i * 256;
        const int r   = t >> 4;             // row 0..127
        const int seg = t & 15;             // 16B segment (8 fp16)
        const uint32_t d = base + (uint32_t)(r * ROW_BYTES + seg * 16);
        cpa16(d + ARR_A, src + (size_t)(I + r) * DIMS + seg * 8);
        cpa16(d + ARR_B, src + (size_t)(J + r) * DIMS + seg * 8);
    }
    CP_COMMIT();
}

// 8 k16-steps of single-product fp16 MMA over one buffer (full k=128)
__device__ __forceinline__ void mma_chunk(uint32_t smb, int buf,
                                          float (*acc)[8][4], int mwarp, int nhalf, int lane) {
    const uint32_t base = smb + (uint32_t)(buf * BUF_BYTES);
    const uint32_t aoff = (uint32_t)((mwarp * 32 + (lane & 15)) * ROW_BYTES + (lane >> 4) * 16);
    const uint32_t boff = (uint32_t)((nhalf * 64 + (lane & 7) + ((lane >> 4) & 1) * 8) * ROW_BYTES
                                     + ((lane >> 3) & 1) * 16);
#pragma unroll
    for (int ks = 0; ks < 8; ks++) {
        uint32_t ah[2][4];
#pragma unroll
        for (int mt = 0; mt < 2; mt++) {
            ldsm4(ah[mt], base + ARR_A + aoff + (uint32_t)(mt * 16 * ROW_BYTES + ks * 32));
        }
#pragma unroll
        for (int ntp = 0; ntp < 4; ntp++) {
            uint32_t bh[4];
            ldsm4(bh, base + ARR_B + boff + (uint32_t)(ntp * 16 * ROW_BYTES + ks * 32));
            // 4 mma into 4 distinct accumulators
            mma_f16(acc[0][2 * ntp],     ah[0], bh[0], bh[1]);
            mma_f16(acc[1][2 * ntp],     ah[1], bh[0], bh[1]);
            mma_f16(acc[0][2 * ntp + 1], ah[0], bh[2], bh[3]);
            mma_f16(acc[1][2 * ntp + 1], ah[1], bh[2], bh[3]);
        }
    }
}

// ---- kernel 2: fused X/Y single-fp16 HMMA tile sweep (triangular grid) ----
__global__ __launch_bounds__(256, 1)
void dcor_mma_kernel() {
    const int t = blockIdx.x;
    int bi = (int)((2.0f * NB + 1.0f
                    - sqrtf((2.0f * NB + 1.0f) * (2.0f * NB + 1.0f) - 8.0f * (float)t)) * 0.5f);
    while (bi > 0 && bi * NB - bi * (bi - 1) / 2 > t) bi--;
    while ((bi + 1) * NB - (bi + 1) * bi / 2 <= t) bi++;
    const int bj = bi + (t - (bi * NB - bi * (bi - 1) / 2));

    extern __shared__ float sm[];
    const uint32_t smb = smem_u32(sm);
    float* NIX = sm + OFF_NIX;
    float* NJX = sm + OFF_NJX;
    float* NIY = sm + OFF_NIY;
    float* NJY = sm + OFF_NJY;
    float* COLPA = sm + OFF_COLPA;
    float* COLPB = sm + OFF_COLPB;
    float* ROWPA = sm + OFF_ROWPA;
    float* ROWPB = sm + OFF_ROWPB;

    const int tid = threadIdx.x, warp = tid >> 5, lane = tid & 31;
    const bool diag = (bi == bj);
    const int I = bi * TILE, J = bj * TILE;
    const int mwarp = warp & 3, nhalf = warp >> 2;
    const unsigned FULL = 0xffffffffu;

    issue_chunk_n(smb, 0, I, J, tid);   // x tiles -> buf0
    issue_chunk_n(smb, 1, I, J, tid);   // y tiles -> buf1

    if (tid < 128) {
        NIX[tid] = g_norm_x[I + tid]; NJX[tid] = g_norm_x[J + tid];
        NIY[tid] = g_norm_y[I + tid]; NJY[tid] = g_norm_y[J + tid];
    }

    float acc_x[2][8][4], acc_y[2][8][4];
#pragma unroll
    for (int mt = 0; mt < 2; mt++)
#pragma unroll
        for (int nt = 0; nt < 8; nt++)
#pragma unroll
            for (int q = 0; q < 4; q++) { acc_x[mt][nt][q] = 0.f; acc_y[mt][nt][q] = 0.f; }

    CP_WAIT(1);           // buf0 (x) ready
    __syncthreads();
    mma_chunk(smb, 0, acc_x, mwarp, nhalf, lane);
    CP_WAIT(0);           // buf1 (y) ready
    __syncthreads();
    mma_chunk(smb, 1, acc_y, mwarp, nhalf, lane);

    // ---- fused epilogue ----
    float njx[8][2], njy[8][2];
#pragma unroll
    for (int nt = 0; nt < 8; nt++) {
        const int col = nhalf * 64 + nt * 8 + (lane & 3) * 2;
        njx[nt][0] = NJX[col]; njx[nt][1] = NJX[col + 1];
        njy[nt][0] = NJY[col]; njy[nt][1] = NJY[col + 1];
    }

    float ssa = 0.f, ssb = 0.f, sab = 0.f;
    float colpa[8][2], colpb[8][2];
    float rowpa[2][2] = {{0.f, 0.f}, {0.f, 0.f}};
    float rowpb[2][2] = {{0.f, 0.f}, {0.f, 0.f}};
#pragma unroll
    for (int nt = 0; nt < 8; nt++) {
        colpa[nt][0] = 0.f; colpa[nt][1] = 0.f;
        colpb[nt][0] = 0.f; colpb[nt][1] = 0.f;
    }

#pragma unroll
    for (int mt = 0; mt < 2; mt++) {
#pragma unroll
        for (int pr = 0; pr < 2; pr++) {
            const int row = mwarp * 32 + mt * 16 + pr * 8 + (lane >> 2);
            const float nIx = NIX[row];
            const float nIy = NIY[row];
#pragma unroll
            for (int nt = 0; nt < 8; nt++) {
                const int col = nhalf * 64 + nt * 8 + (lane & 3) * 2;
                float gx0 = acc_x[mt][nt][pr * 2 + 0];
                float gx1 = acc_x[mt][nt][pr * 2 + 1];
                float gy0 = acc_y[mt][nt][pr * 2 + 0];
                float gy1 = acc_y[mt][nt][pr * 2 + 1];
                float sqx0 = fmaf(-2.f, gx0, nIx + njx[nt][0]);
                float sqx1 = fmaf(-2.f, gx1, nIx + njx[nt][1]);
                float sqy0 = fmaf(-2.f, gy0, nIy + njy[nt][0]);
                float sqy1 = fmaf(-2.f, gy1, nIy + njy[nt][1]);
                float dx0 = (sqx0 > 0.f) ? sqx0 * rsqrtf(sqx0) : 0.f;
                float dx1 = (sqx1 > 0.f) ? sqx1 * rsqrtf(sqx1) : 0.f;
                float dy0 = (sqy0 > 0.f) ? sqy0 * rsqrtf(sqy0) : 0.f;
                float dy1 = (sqy1 > 0.f) ? sqy1 * rsqrtf(sqy1) : 0.f;
                if (diag) {
                    if (row == col)     { dx0 = 0.f; dy0 = 0.f; }
                    if (row == col + 1) { dx1 = 0.f; dy1 = 0.f; }
                }
                ssa = fmaf(dx0, dx0, ssa); ssa = fmaf(dx1, dx1, ssa);
                ssb = fmaf(dy0, dy0, ssb); ssb = fmaf(dy1, dy1, ssb);
                sab = fmaf(dx0, dy0, sab); sab = fmaf(dx1, dy1, sab);
                rowpa[mt][pr] += dx0 + dx1;
                rowpb[mt][pr] += dy0 + dy1;
                colpa[nt][0] += dx0; colpa[nt][1] += dx1;
                colpb[nt][0] += dy0; colpb[nt][1] += dy1;
            }
        }
    }
    double s_aa = (double)ssa, s_bb = (double)ssb, s_ab = (double)sab;

    // col sums: reduce over the 8 row-lanes
#pragma unroll
    for (int nt = 0; nt < 8; nt++)
#pragma unroll
        for (int c2 = 0; c2 < 2; c2++) {
            float va = colpa[nt][c2], vb = colpb[nt][c2];
            va += __shfl_down_sync(FULL, va, 16);
            va += __shfl_down_sync(FULL, va, 8);
            va += __shfl_down_sync(FULL, va, 4);
            vb += __shfl_down_sync(FULL, vb, 16);
            vb += __shfl_down_sync(FULL, vb, 8);
            vb += __shfl_down_sync(FULL, vb, 4);
            colpa[nt][c2] = va; colpb[nt][c2] = vb;
        }
    if (lane < 4) {
#pragma unroll
        for (int nt = 0; nt < 8; nt++) {
            const int col = nhalf * 64 + nt * 8 + lane * 2;
            COLPA[mwarp * 128 + col]     = colpa[nt][0];
            COLPA[mwarp * 128 + col + 1] = colpa[nt][1];
            COLPB[mwarp * 128 + col]     = colpb[nt][0];
            COLPB[mwarp * 128 + col + 1] = colpb[nt][1];
        }
    }
    // row sums: reduce over the 4 col-lanes
#pragma unroll
    for (int mt = 0; mt < 2; mt++)
#pragma unroll
        for (int pr = 0; pr < 2; pr++) {
            float va = rowpa[mt][pr], vb = rowpb[mt][pr];
            va += __shfl_down_sync(FULL, va, 1);
            va += __shfl_down_sync(FULL, va, 2);
            rowpa[mt][pr] = va;
            vb += __shfl_down_sync(FULL, vb, 1);
            vb += __shfl_down_sync(FULL, vb, 2);
            rowpb[mt][pr] = vb;
        }
    if ((lane & 3) == 0) {
#pragma unroll
        for (int mt = 0; mt < 2; mt++)
#pragma unroll
            for (int pr = 0; pr < 2; pr++) {
                const int row = mwarp * 32 + mt * 16 + pr * 8 + (lane >> 2);
                ROWPA[nhalf * 128 + row] = rowpa[mt][pr];
                ROWPB[nhalf * 128 + row] = rowpb[mt][pr];
            }
    }
    __syncthreads();
    if (tid < 128) {
        float csa = COLPA[tid] + COLPA[128 + tid] + COLPA[256 + tid] + COLPA[384 + tid];
        float csb = COLPB[tid] + COLPB[128 + tid] + COLPB[256 + tid] + COLPB[384 + tid];
        float rsa = ROWPA[tid] + ROWPA[128 + tid];
        float rsb = ROWPB[tid] + ROWPB[128 + tid];
        atomicAdd(&g_rs_a[I + tid], (double)rsa);
        atomicAdd(&g_rs_b[I + tid], (double)rsb);
        if (!diag) {
            atomicAdd(&g_rs_a[J + tid], (double)csa);
            atomicAdd(&g_rs_b[J + tid], (double)csb);
        }
    }

    // ---- block scalar reduction ----
    const double w = diag ? 1.0 : 2.0;
    s_aa *= w; s_bb *= w; s_ab *= w;
#pragma unroll
    for (int o = 16; o; o >>= 1) {
        s_aa += __shfl_down_sync(FULL, s_aa, o);
        s_bb += __shfl_down_sync(FULL, s_bb, o);
        s_ab += __shfl_down_sync(FULL, s_ab, o);
    }
    __shared__ double redS[3][8];
    if (lane == 0) { redS[0][warp] = s_aa; redS[1][warp] = s_bb; redS[2][warp] = s_ab; }
    __syncthreads();
    if (tid == 0) {
        double a = 0, b = 0, c = 0;
#pragma unroll
        for (int k = 0; k < 8; k++) { a += redS[0][k]; b += redS[1][k]; c += redS[2][k]; }
        atomicAdd(&g_S[0], a);
        atomicAdd(&g_S[1], b);
        atomicAdd(&g_S[2], c);
    }
}

// ---- kernel 3: combine + final scalar ----
__global__ void finalize_kernel(float* __restrict__ out) {
    int tid = threadIdx.x;
    double dAB = 0, dAA = 0, dBB = 0, Ta = 0, Tb = 0;
    for (int i = tid; i < NPTS; i += 256) {
        double a = g_rs_a[i], b = g_rs_b[i];
        dAB += a * b; dAA += a * a; dBB += b * b; Ta += a; Tb += b;
    }
    const unsigned FULL = 0xffffffffu;
#pragma unroll
    for (int o = 16; o; o >>= 1) {
        dAB += __shfl_down_sync(FULL, dAB, o);
        dAA += __shfl_down_sync(FULL, dAA, o);
        dBB += __shfl_down_sync(FULL, dBB, o);
        Ta  += __shfl_down_sync(FULL, Ta,  o);
        Tb  += __shfl_down_sync(FULL, Tb,  o);
    }
    __shared__ double red[5][8];
    int wid = tid >> 5, lane = tid & 31;
    if (lane == 0) {
        red[0][wid] = dAB; red[1][wid] = dAA; red[2][wid] = dBB;
        red[3][wid] = Ta;  red[4][wid] = Tb;
    }
    __syncthreads();
    if (tid == 0) {
        double sAB = 0, sAA = 0, sBB = 0, ta = 0, tb = 0;
#pragma unroll
        for (int k = 0; k < 8; k++) {
            sAB += red[0][k]; sAA += red[1][k]; sBB += red[2][k];
            ta  += red[3][k]; tb  += red[4][k];
        }
        const double n = (double)NPTS;
        const double inv_n2 = 1.0 / (n * n);
        double xy = (g_S[2] - (2.0 / n) * sAB + ta * tb * inv_n2) * inv_n2;
        double xx = (g_S[0] - (2.0 / n) * sAA + ta * ta * inv_n2) * inv_n2;
        double yy = (g_S[1] - (2.0 / n) * sBB + tb * tb * inv_n2) * inv_n2;
        xy = fmax(xy, 0.0); xx = fmax(xx, 0.0); yy = fmax(yy, 0.0);
        double dcor = -sqrt(xy) / sqrt(sqrt(xx) * sqrt(yy));
        out[0] = (float)dcor;
    }
}

extern "C" void kernel_launch(void* const* d_in, const int* in_sizes, int n_in,
                              void* d_out, int out_size) {
    (void)in_sizes; (void)n_in; (void)out_size;
    const float* x = (const float*)d_in[0];
    const float* y = (const float*)d_in[1];
    float* out = (float*)d_out;

    cudaFuncSetAttribute(dcor_mma_kernel,
                         cudaFuncAttributeMaxDynamicSharedMemorySize, SMEM_BYTES);

    prep_kernel<<<NPTS / 8, 256>>>(x, y);
    dcor_mma_kernel<<<NTILES, 256, SMEM_BYTES>>>();
    finalize_kernel<<<1, 256>>>(out);
}

// round 15
// speedup vs baseline: 1.7292x; 1.0253x over previous
#include <cuda_runtime.h>
#include <cuda_fp16.h>
#include <math.h>
#include <stdint.h>

#define NPTS 8192
#define DIMS 128
#define TROWS 128              // tile rows (I)
#define TCOLS 64               // tile cols (J)
#define NTILES 4160            // sum_{bi<64} (128 - 2*bi)

// ---- smem layout (bytes) ----
#define ROW_BYTES 144                    // 64 fp16 = 128B + 16B pad
#define ARRA_BYTES (TROWS * ROW_BYTES)   // 18432
#define ARRB_BYTES (TCOLS * ROW_BYTES)   // 9216
#define ARR_A 0
#define ARR_B ARRA_BYTES
#define BUF_BYTES (ARRA_BYTES + ARRB_BYTES)   // 27648
// float-indexed tail after 2 buffers (55296 B = 13824 floats)
#define OFF_NIX   13824
#define OFF_NIY   (OFF_NIX + 128)
#define OFF_NJX   (OFF_NIY + 128)
#define OFF_NJY   (OFF_NJX + 64)
#define OFF_COLPA (OFF_NJY + 64)        // [4 mwarp][64]
#define OFF_COLPB (OFF_COLPA + 256)
#define OFF_ROWPA (OFF_COLPB + 256)     // [2 nhalf][128]
#define OFF_ROWPB (OFF_ROWPA + 256)
#define SMEM_FLOATS (OFF_ROWPB + 256)   // 15168
#define SMEM_BYTES  (SMEM_FLOATS * 4)   // 60672

// ---- global scratch ----
__device__ __align__(16) __half g_x16[NPTS * DIMS];
__device__ __align__(16) __half g_y16[NPTS * DIMS];
__device__ float  g_norm_x[NPTS];
__device__ float  g_norm_y[NPTS];
__device__ double g_rs_a[NPTS];
__device__ double g_rs_b[NPTS];
__device__ double g_S[3];

// ---- helpers ----
__device__ __forceinline__ void mma_f16(float* d,
                                        const uint32_t* a, uint32_t b0, uint32_t b1) {
    asm volatile(
        "mma.sync.aligned.m16n8k16.row.col.f32.f16.f16.f32 "
        "{%0,%1,%2,%3}, {%4,%5,%6,%7}, {%8,%9}, {%0,%1,%2,%3};"
        : "+f"(d[0]), "+f"(d[1]), "+f"(d[2]), "+f"(d[3])
        : "r"(a[0]), "r"(a[1]), "r"(a[2]), "r"(a[3]), "r"(b0), "r"(b1));
}

__device__ __forceinline__ void ldsm4(uint32_t* r, uint32_t addr) {
    asm volatile("ldmatrix.sync.aligned.m8n8.x4.shared.b16 {%0,%1,%2,%3}, [%4];"
        : "=r"(r[0]), "=r"(r[1]), "=r"(r[2]), "=r"(r[3]) : "r"(addr));
}

__device__ __forceinline__ uint32_t smem_u32(const void* p) {
    uint32_t a;
    asm("{ .reg .u64 t; cvta.to.shared.u64 t, %1; cvt.u32.u64 %0, t; }" : "=r"(a) : "l"(p));
    return a;
}
__device__ __forceinline__ void cpa16(uint32_t dst, const void* src) {
    asm volatile("cp.async.ca.shared.global [%0], [%1], 16;" :: "r"(dst), "l"(src));
}
#define CP_COMMIT() asm volatile("cp.async.commit_group;" ::: "memory")
#define CP_WAIT(N)  asm volatile("cp.async.wait_group %0;" :: "n"(N) : "memory")

// ---- kernel 1: round x/y to fp16 + norms of rounded values + zero scratch ----
__global__ __launch_bounds__(256, 4)
void prep_kernel(const float* __restrict__ x, const float* __restrict__ y) {
    const int warp = threadIdx.x >> 5, lane = threadIdx.x & 31;
    const int r = blockIdx.x * 8 + warp;
    if (blockIdx.x == 0 && threadIdx.x < 3) g_S[threadIdx.x] = 0.0;

    const float4 vx = reinterpret_cast<const float4*>(x + (size_t)r * DIMS)[lane];
    const float4 vy = reinterpret_cast<const float4*>(y + (size_t)r * DIMS)[lane];

    __half hx[4], hy[4];
    hx[0] = __float2half_rn(vx.x); hx[1] = __float2half_rn(vx.y);
    hx[2] = __float2half_rn(vx.z); hx[3] = __float2half_rn(vx.w);
    hy[0] = __float2half_rn(vy.x); hy[1] = __float2half_rn(vy.y);
    hy[2] = __float2half_rn(vy.z); hy[3] = __float2half_rn(vy.w);
    *reinterpret_cast<uint2*>(g_x16 + (size_t)r * DIMS + lane * 4) = *reinterpret_cast<uint2*>(hx);
    *reinterpret_cast<uint2*>(g_y16 + (size_t)r * DIMS + lane * 4) = *reinterpret_cast<uint2*>(hy);

    float sx = 0.f, sy = 0.f;
#pragma unroll
    for (int q = 0; q < 4; q++) {
        float fx = __half2float(hx[q]), fy = __half2float(hy[q]);
        sx = fmaf(fx, fx, sx);
        sy = fmaf(fy, fy, sy);
    }
    const unsigned FULL = 0xffffffffu;
#pragma unroll
    for (int o = 16; o; o >>= 1) {
        sx += __shfl_xor_sync(FULL, sx, o);
        sy += __shfl_xor_sync(FULL, sy, o);
    }
    if (lane == 0) {
        g_norm_x[r] = sx; g_norm_y[r] = sy;
        g_rs_a[r] = 0.0;  g_rs_b[r] = 0.0;
    }
}

// issue cp.async for chunk n: matrix = n&1, kc = (n>>1)*64, buf = n&1
// A: 128 rows at I (1024 x 16B), B: 64 rows at J (512 x 16B) -> 1536 = 6*256
__device__ __forceinline__ void issue_chunk_n(uint32_t smb, int n, int I, int J, int tid) {
    const __half* src = (n & 1) ? g_y16 : g_x16;
    const int kc = (n >> 1) * 64;
    const uint32_t base = smb + (uint32_t)((n & 1) * BUF_BYTES);
#pragma unroll
    for (int i = 0; i < 6; i++) {
        const int t = tid + i * 256;
        if (t < 1024) {
            const int r = t >> 3, seg = t & 7;
            cpa16(base + ARR_A + (uint32_t)(r * ROW_BYTES + seg * 16),
                  src + (size_t)(I + r) * DIMS + kc + seg * 8);
        } else {
            const int u = t - 1024;
            const int r = u >> 3, seg = u & 7;
            cpa16(base + ARR_B + (uint32_t)(r * ROW_BYTES + seg * 16),
                  src + (size_t)(J + r) * DIMS + kc + seg * 8);
        }
    }
    CP_COMMIT();
}

// 4 k16-steps over one 64-k chunk; warp sub-tile 32 rows x 32 cols
__device__ __forceinline__ void mma_chunk(uint32_t smb, int buf,
                                          float (*acc)[4][4], int mwarp, int nhalf, int lane) {
    const uint32_t base = smb + (uint32_t)(buf * BUF_BYTES);
    const uint32_t aoff = (uint32_t)((mwarp * 32 + (lane & 15)) * ROW_BYTES + (lane >> 4) * 16);
    const uint32_t boff = (uint32_t)((nhalf * 32 + (lane & 7) + ((lane >> 4) & 1) * 8) * ROW_BYTES
                                     + ((lane >> 3) & 1) * 16);
#pragma unroll
    for (int ks = 0; ks < 4; ks++) {
        uint32_t ah[2][4];
#pragma unroll
        for (int mt = 0; mt < 2; mt++)
            ldsm4(ah[mt], base + ARR_A + aoff + (uint32_t)(mt * 16 * ROW_BYTES + ks * 32));
#pragma unroll
        for (int ntp = 0; ntp < 2; ntp++) {
            uint32_t bh[4];
            ldsm4(bh, base + ARR_B + boff + (uint32_t)(ntp * 16 * ROW_BYTES + ks * 32));
            mma_f16(acc[0][2 * ntp],     ah[0], bh[0], bh[1]);
            mma_f16(acc[1][2 * ntp],     ah[1], bh[0], bh[1]);
            mma_f16(acc[0][2 * ntp + 1], ah[0], bh[2], bh[3]);
            mma_f16(acc[1][2 * ntp + 1], ah[1], bh[2], bh[3]);
        }
    }
}

// ---- kernel 2: fused X/Y fp16 HMMA, 128x64 tiles, 2 CTAs/SM ----
__global__ __launch_bounds__(256, 2)
void dcor_mma_kernel() {
    // decode tile index: for row block bi, col blocks bjc in [2*bi, 128)
    // cum(bi) = bi*(129 - bi)
    const int t = blockIdx.x;
    int bi = (int)((129.0f - sqrtf(129.0f * 129.0f - 4.0f * (float)t)) * 0.5f);
    while (bi > 0 && bi * (129 - bi) > t) bi--;
    while ((bi + 1) * (129 - (bi + 1)) <= t) bi++;
    const int bjc = 2 * bi + (t - bi * (129 - bi));

    extern __shared__ float sm[];
    const uint32_t smb = smem_u32(sm);
    float* NIX = sm + OFF_NIX;
    float* NIY = sm + OFF_NIY;
    float* NJX = sm + OFF_NJX;
    float* NJY = sm + OFF_NJY;
    float* COLPA = sm + OFF_COLPA;
    float* COLPB = sm + OFF_COLPB;
    float* ROWPA = sm + OFF_ROWPA;
    float* ROWPB = sm + OFF_ROWPB;

    const int tid = threadIdx.x, warp = tid >> 5, lane = tid & 31;
    const int I = bi * TROWS, J = bjc * TCOLS;
    const int dof = I - J;          // mask: include element iff col - row > dof
    const int mwarp = warp & 3;     // row quarter (32 rows)
    const int nhalf = warp >> 2;    // col half (32 cols)
    const unsigned FULL = 0xffffffffu;

    issue_chunk_n(smb, 0, I, J, tid);
    issue_chunk_n(smb, 1, I, J, tid);

    if (tid < 128) { NIX[tid] = g_norm_x[I + tid]; NIY[tid] = g_norm_y[I + tid]; }
    else if (tid < 192) {
        NJX[tid - 128] = g_norm_x[J + tid - 128];
        NJY[tid - 128] = g_norm_y[J + tid - 128];
    }

    float acc_x[2][4][4], acc_y[2][4][4];
#pragma unroll
    for (int mt = 0; mt < 2; mt++)
#pragma unroll
        for (int nt = 0; nt < 4; nt++)
#pragma unroll
            for (int q = 0; q < 4; q++) { acc_x[mt][nt][q] = 0.f; acc_y[mt][nt][q] = 0.f; }

    // chunks: x(k0), y(k0), x(k64), y(k64) through 2 alternating buffers
#pragma unroll
    for (int c = 0; c < 4; c++) {
        if (c < 3) { CP_WAIT(1); } else { CP_WAIT(0); }
        __syncthreads();
        mma_chunk(smb, c & 1, (c & 1) ? acc_y : acc_x, mwarp, nhalf, lane);
        if (c < 2) {
            __syncthreads();
            issue_chunk_n(smb, c + 2, I, J, tid);
        }
    }

    // ---- fused epilogue (upper-triangle masked, every element weight 2) ----
    float njx[4][2], njy[4][2];
#pragma unroll
    for (int nt = 0; nt < 4; nt++) {
        const int col = nhalf * 32 + nt * 8 + (lane & 3) * 2;
        njx[nt][0] = NJX[col]; njx[nt][1] = NJX[col + 1];
        njy[nt][0] = NJY[col]; njy[nt][1] = NJY[col + 1];
    }

    float ssa = 0.f, ssb = 0.f, sab = 0.f;
    float colpa[4][2], colpb[4][2];
    float rowpa[2][2] = {{0.f, 0.f}, {0.f, 0.f}};
    float rowpb[2][2] = {{0.f, 0.f}, {0.f, 0.f}};
#pragma unroll
    for (int nt = 0; nt < 4; nt++) {
        colpa[nt][0] = 0.f; colpa[nt][1] = 0.f;
        colpb[nt][0] = 0.f; colpb[nt][1] = 0.f;
    }

#pragma unroll
    for (int mt = 0; mt < 2; mt++) {
#pragma unroll
        for (int pr = 0; pr < 2; pr++) {
            const int row = mwarp * 32 + mt * 16 + pr * 8 + (lane >> 2);
            const float nIx = NIX[row];
            const float nIy = NIY[row];
#pragma unroll
            for (int nt = 0; nt < 4; nt++) {
                const int col = nhalf * 32 + nt * 8 + (lane & 3) * 2;
                float gx0 = acc_x[mt][nt][pr * 2 + 0];
                float gx1 = acc_x[mt][nt][pr * 2 + 1];
                float gy0 = acc_y[mt][nt][pr * 2 + 0];
                float gy1 = acc_y[mt][nt][pr * 2 + 1];
                float sqx0 = fmaf(-2.f, gx0, nIx + njx[nt][0]);
                float sqx1 = fmaf(-2.f, gx1, nIx + njx[nt][1]);
                float sqy0 = fmaf(-2.f, gy0, nIy + njy[nt][0]);
                float sqy1 = fmaf(-2.f, gy1, nIy + njy[nt][1]);
                float dx0 = (sqx0 > 0.f) ? sqx0 * rsqrtf(sqx0) : 0.f;
                float dx1 = (sqx1 > 0.f) ? sqx1 * rsqrtf(sqx1) : 0.f;
                float dy0 = (sqy0 > 0.f) ? sqy0 * rsqrtf(sqy0) : 0.f;
                float dy1 = (sqy1 > 0.f) ? sqy1 * rsqrtf(sqy1) : 0.f;
                // upper-triangle mask: include iff global col > global row
                if (col - row <= dof)     { dx0 = 0.f; dy0 = 0.f; }
                if (col + 1 - row <= dof) { dx1 = 0.f; dy1 = 0.f; }
                ssa = fmaf(dx0, dx0, ssa); ssa = fmaf(dx1, dx1, ssa);
                ssb = fmaf(dy0, dy0, ssb); ssb = fmaf(dy1, dy1, ssb);
                sab = fmaf(dx0, dy0, sab); sab = fmaf(dx1, dy1, sab);
                rowpa[mt][pr] += dx0 + dx1;
                rowpb[mt][pr] += dy0 + dy1;
                colpa[nt][0] += dx0; colpa[nt][1] += dx1;
                colpb[nt][0] += dy0; colpb[nt][1] += dy1;
            }
        }
    }
    double s_aa = (double)ssa, s_bb = (double)ssb, s_ab = (double)sab;

    // col sums: reduce over the 8 row-lanes
#pragma unroll
    for (int nt = 0; nt < 4; nt++)
#pragma unroll
        for (int c2 = 0; c2 < 2; c2++) {
            float va = colpa[nt][c2], vb = colpb[nt][c2];
            va += __shfl_down_sync(FULL, va, 16);
            va += __shfl_down_sync(FULL, va, 8);
            va += __shfl_down_sync(FULL, va, 4);
            vb += __shfl_down_sync(FULL, vb, 16);
            vb += __shfl_down_sync(FULL, vb, 8);
            vb += __shfl_down_sync(FULL, vb, 4);
            colpa[nt][c2] = va; colpb[nt][c2] = vb;
        }
    if (lane < 4) {
#pragma unroll
        for (int nt = 0; nt < 4; nt++) {
            const int col = nhalf * 32 + nt * 8 + lane * 2;
            COLPA[mwarp * 64 + col]     = colpa[nt][0];
            COLPA[mwarp * 64 + col + 1] = colpa[nt][1];
            COLPB[mwarp * 64 + col]     = colpb[nt][0];
            COLPB[mwarp * 64 + col + 1] = colpb[nt][1];
        }
    }
    // row sums: reduce over the 4 col-lanes
#pragma unroll
    for (int mt = 0; mt < 2; mt++)
#pragma unroll
        for (int pr = 0; pr < 2; pr++) {
            float va = rowpa[mt][pr], vb = rowpb[mt][pr];
            va += __shfl_down_sync(FULL, va, 1);
            va += __shfl_down_sync(FULL, va, 2);
            rowpa[mt][pr] = va;
            vb += __shfl_down_sync(FULL, vb, 1);
            vb += __shfl_down_sync(FULL, vb, 2);
            rowpb[mt][pr] = vb;
        }
    if ((lane & 3) == 0) {
#pragma unroll
        for (int mt = 0; mt < 2; mt++)
#pragma unroll
            for (int pr = 0; pr < 2; pr++) {
                const int row = mwarp * 32 + mt * 16 + pr * 8 + (lane >> 2);
                ROWPA[nhalf * 128 + row] = rowpa[mt][pr];
                ROWPB[nhalf * 128 + row] = rowpb[mt][pr];
            }
    }
    __syncthreads();
    if (tid < 128) {
        float rsa = ROWPA[tid] + ROWPA[128 + tid];
        float rsb = ROWPB[tid] + ROWPB[128 + tid];
        atomicAdd(&g_rs_a[I + tid], (double)rsa);
        atomicAdd(&g_rs_b[I + tid], (double)rsb);
    } else if (tid < 192) {
        const int c = tid - 128;
        float csa = COLPA[c] + COLPA[64 + c] + COLPA[128 + c] + COLPA[192 + c];
        float csb = COLPB[c] + COLPB[64 + c] + COLPB[128 + c] + COLPB[192 + c];
        atomicAdd(&g_rs_a[J + c], (double)csa);
        atomicAdd(&g_rs_b[J + c], (double)csb);
    }

    // ---- block scalar reduction (weight 2 for every computed element) ----
    s_aa *= 2.0; s_bb *= 2.0; s_ab *= 2.0;
#pragma unroll
    for (int o = 16; o; o >>= 1) {
        s_aa += __shfl_down_sync(FULL, s_aa, o);
        s_bb += __shfl_down_sync(FULL, s_bb, o);
        s_ab += __shfl_down_sync(FULL, s_ab, o);
    }
    __shared__ double redS[3][8];
    if (lane == 0) { redS[0][warp] = s_aa; redS[1][warp] = s_bb; redS[2][warp] = s_ab; }
    __syncthreads();
    if (tid == 0) {
        double a = 0, b = 0, c = 0;
#pragma unroll
        for (int k = 0; k < 8; k++) { a += redS[0][k]; b += redS[1][k]; c += redS[2][k]; }
        atomicAdd(&g_S[0], a);
        atomicAdd(&g_S[1], b);
        atomicAdd(&g_S[2], c);
    }
}

// ---- kernel 3: combine + final scalar ----
__global__ void finalize_kernel(float* __restrict__ out) {
    int tid = threadIdx.x;
    double dAB = 0, dAA = 0, dBB = 0, Ta = 0, Tb = 0;
    for (int i = tid; i < NPTS; i += 256) {
        double a = g_rs_a[i], b = g_rs_b[i];
        dAB += a * b; dAA += a * a; dBB += b * b; Ta += a; Tb += b;
    }
    const unsigned FULL = 0xffffffffu;
#pragma unroll
    for (int o = 16; o; o >>= 1) {
        dAB += __shfl_down_sync(FULL, dAB, o);
        dAA += __shfl_down_sync(FULL, dAA, o);
        dBB += __shfl_down_sync(FULL, dBB, o);
        Ta  += __shfl_down_sync(FULL, Ta,  o);
        Tb  += __shfl_down_sync(FULL, Tb,  o);
    }
    __shared__ double red[5][8];
    int wid = tid >> 5, lane = tid & 31;
    if (lane == 0) {
        red[0][wid] = dAB; red[1][wid] = dAA; red[2][wid] = dBB;
        red[3][wid] = Ta;  red[4][wid] = Tb;
    }
    __syncthreads();
    if (tid == 0) {
        double sAB = 0, sAA = 0, sBB = 0, ta = 0, tb = 0;
#pragma unroll
        for (int k = 0; k < 8; k++) {
            sAB += red[0][k]; sAA += red[1][k]; sBB += red[2][k];
            ta  += red[3][k]; tb  += red[4][k];
        }
        const double n = (double)NPTS;
        const double inv_n2 = 1.0 / (n * n);
        double xy = (g_S[2] - (2.0 / n) * sAB + ta * tb * inv_n2) * inv_n2;
        double xx = (g_S[0] - (2.0 / n) * sAA + ta * ta * inv_n2) * inv_n2;
        double yy = (g_S[1] - (2.0 / n) * sBB + tb * tb * inv_n2) * inv_n2;
        xy = fmax(xy, 0.0); xx = fmax(xx, 0.0); yy = fmax(yy, 0.0);
        double dcor = -sqrt(xy) / sqrt(sqrt(xx) * sqrt(yy));
        out[0] = (float)dcor;
    }
}

extern "C" void kernel_launch(void* const* d_in, const int* in_sizes, int n_in,
                              void* d_out, int out_size) {
    (void)in_sizes; (void)n_in; (void)out_size;
    const float* x = (const float*)d_in[0];
    const float* y = (const float*)d_in[1];
    float* out = (float*)d_out;

    cudaFuncSetAttribute(dcor_mma_kernel,
                         cudaFuncAttributeMaxDynamicSharedMemorySize, SMEM_BYTES);

    prep_kernel<<<NPTS / 8, 256>>>(x, y);
    dcor_mma_kernel<<<NTILES, 256, SMEM_BYTES>>>();
    finalize_kernel<<<1, 256>>>(out);
}

// round 17
// speedup vs baseline: 1.7461x; 1.0098x over previous
#include <cuda_runtime.h>
#include <cuda_fp16.h>
#include <math.h>
#include <stdint.h>

#define NPTS 8192
#define DIMS 128
#define TILE 128
#define NB   64
#define GRP  4
#define NGROUPS 544            // sum_{bi<64} ceil((64-bi)/4)

// ---- smem layout ----
#define ROW_BYTES 272                     // 128 fp16 = 256B + 16B pad
#define ARR_BYTES (TILE * ROW_BYTES)      // 34816 per matrix tile
#define OFF_AX 0
#define OFF_AY ARR_BYTES                  // 34816
#define OFF_BUF (2 * ARR_BYTES)           // 69632; buf b: BX at +b*2*ARR, BY at +ARR
#define BUF_BYTES (2 * ARR_BYTES)
#define TAIL_F (6 * ARR_BYTES / 4)        // float index 52224
#define OFF_NIX   TAIL_F
#define OFF_NIY   (OFF_NIX + 128)
#define OFF_NJX   (OFF_NIY + 128)
#define OFF_NJY   (OFF_NJX + 128)
#define OFF_COLPA (OFF_NJY + 128)         // [4 mwarp][128]
#define OFF_COLPB (OFF_COLPA + 512)
#define OFF_ROWPA (OFF_COLPB + 512)       // [2 nhalf][128]
#define OFF_ROWPB (OFF_ROWPA + 256)
#define SMEM_FLOATS (OFF_ROWPB + 256)     // 54272
#define SMEM_BYTES  (SMEM_FLOATS * 4)     // 217088

// ---- global scratch ----
__device__ __align__(16) __half g_x16[NPTS * DIMS];
__device__ __align__(16) __half g_y16[NPTS * DIMS];
__device__ float  g_norm_x[NPTS];
__device__ float  g_norm_y[NPTS];
__device__ double g_rs_a[NPTS];
__device__ double g_rs_b[NPTS];
__device__ double g_S[3];

// ---- helpers ----
__device__ __forceinline__ void mma_f16(float* d,
                                        const uint32_t* a, uint32_t b0, uint32_t b1) {
    asm volatile(
        "mma.sync.aligned.m16n8k16.row.col.f32.f16.f16.f32 "
        "{%0,%1,%2,%3}, {%4,%5,%6,%7}, {%8,%9}, {%0,%1,%2,%3};"
        : "+f"(d[0]), "+f"(d[1]), "+f"(d[2]), "+f"(d[3])
        : "r"(a[0]), "r"(a[1]), "r"(a[2]), "r"(a[3]), "r"(b0), "r"(b1));
}

__device__ __forceinline__ void ldsm4(uint32_t* r, uint32_t addr) {
    asm volatile("ldmatrix.sync.aligned.m8n8.x4.shared.b16 {%0,%1,%2,%3}, [%4];"
        : "=r"(r[0]), "=r"(r[1]), "=r"(r[2]), "=r"(r[3]) : "r"(addr));
}

__device__ __forceinline__ uint32_t smem_u32(const void* p) {
    uint32_t a;
    asm("{ .reg .u64 t; cvta.to.shared.u64 t, %1; cvt.u32.u64 %0, t; }" : "=r"(a) : "l"(p));
    return a;
}
__device__ __forceinline__ void cpa16(uint32_t dst, const void* src) {
    asm volatile("cp.async.ca.shared.global [%0], [%1], 16;" :: "r"(dst), "l"(src));
}
#define CP_COMMIT() asm volatile("cp.async.commit_group;" ::: "memory")
#define CP_WAIT(N)  asm volatile("cp.async.wait_group %0;" :: "n"(N) : "memory")

// ---- kernel 1: round to fp16 + norms of rounded values + zero scratch ----
__global__ __launch_bounds__(256, 4)
void prep_kernel(const float* __restrict__ x, const float* __restrict__ y) {
    const int warp = threadIdx.x >> 5, lane = threadIdx.x & 31;
    const int r = blockIdx.x * 8 + warp;
    if (blockIdx.x == 0 && threadIdx.x < 3) g_S[threadIdx.x] = 0.0;

    const float4 vx = reinterpret_cast<const float4*>(x + (size_t)r * DIMS)[lane];
    const float4 vy = reinterpret_cast<const float4*>(y + (size_t)r * DIMS)[lane];

    __half hx[4], hy[4];
    hx[0] = __float2half_rn(vx.x); hx[1] = __float2half_rn(vx.y);
    hx[2] = __float2half_rn(vx.z); hx[3] = __float2half_rn(vx.w);
    hy[0] = __float2half_rn(vy.x); hy[1] = __float2half_rn(vy.y);
    hy[2] = __float2half_rn(vy.z); hy[3] = __float2half_rn(vy.w);
    *reinterpret_cast<uint2*>(g_x16 + (size_t)r * DIMS + lane * 4) = *reinterpret_cast<uint2*>(hx);
    *reinterpret_cast<uint2*>(g_y16 + (size_t)r * DIMS + lane * 4) = *reinterpret_cast<uint2*>(hy);

    float sx = 0.f, sy = 0.f;
#pragma unroll
    for (int q = 0; q < 4; q++) {
        float fx = __half2float(hx[q]), fy = __half2float(hy[q]);
        sx = fmaf(fx, fx, sx);
        sy = fmaf(fy, fy, sy);
    }
    const unsigned FULL = 0xffffffffu;
#pragma unroll
    for (int o = 16; o; o >>= 1) {
        sx += __shfl_xor_sync(FULL, sx, o);
        sy += __shfl_xor_sync(FULL, sy, o);
    }
    if (lane == 0) {
        g_norm_x[r] = sx; g_norm_y[r] = sy;
        g_rs_a[r] = 0.0;  g_rs_b[r] = 0.0;
    }
}

// load A tiles (x and y) for row block I
__device__ __forceinline__ void issue_A(uint32_t smb, int I, int tid) {
#pragma unroll
    for (int i = 0; i < 8; i++) {          // 128 rows * 16 segs / 256 threads
        const int t = tid + i * 256;
        const int r = t >> 4, seg = t & 15;
        const uint32_t d = smb + (uint32_t)(r * ROW_BYTES + seg * 16);
        const size_t so = (size_t)(I + r) * DIMS + seg * 8;
        cpa16(d + OFF_AX, g_x16 + so);
        cpa16(d + OFF_AY, g_y16 + so);
    }
}

// load B tiles (x and y) for col block J into buffer `buf`
__device__ __forceinline__ void issue_B(uint32_t smb, int J, int buf, int tid) {
    const uint32_t base = smb + (uint32_t)(OFF_BUF + buf * BUF_BYTES);
#pragma unroll
    for (int i = 0; i < 8; i++) {
        const int t = tid + i * 256;
        const int r = t >> 4, seg = t & 15;
        const uint32_t d = base + (uint32_t)(r * ROW_BYTES + seg * 16);
        const size_t so = (size_t)(J + r) * DIMS + seg * 8;
        cpa16(d, g_x16 + so);
        cpa16(d + ARR_BYTES, g_y16 + so);
    }
}

// 8 k16-steps of fp16 MMA: A at aBase, B at bBase (both 128 rows x 272B)
__device__ __forceinline__ void mma_mat(uint32_t smb, uint32_t aBase, uint32_t bBase,
                                        float (*acc)[8][4], int mwarp, int nhalf, int lane) {
    const uint32_t aoff = (uint32_t)((mwarp * 32 + (lane & 15)) * ROW_BYTES + (lane >> 4) * 16);
    const uint32_t boff = (uint32_t)((nhalf * 64 + (lane & 7) + ((lane >> 4) & 1) * 8) * ROW_BYTES
                                     + ((lane >> 3) & 1) * 16);
#pragma unroll
    for (int ks = 0; ks < 8; ks++) {
        uint32_t ah[2][4];
#pragma unroll
        for (int mt = 0; mt < 2; mt++)
            ldsm4(ah[mt], smb + aBase + aoff + (uint32_t)(mt * 16 * ROW_BYTES + ks * 32));
#pragma unroll
        for (int ntp = 0; ntp < 4; ntp++) {
            uint32_t bh[4];
            ldsm4(bh, smb + bBase + boff + (uint32_t)(ntp * 16 * ROW_BYTES + ks * 32));
            mma_f16(acc[0][2 * ntp],     ah[0], bh[0], bh[1]);
            mma_f16(acc[1][2 * ntp],     ah[1], bh[0], bh[1]);
            mma_f16(acc[0][2 * ntp + 1], ah[0], bh[2], bh[3]);
            mma_f16(acc[1][2 * ntp + 1], ah[1], bh[2], bh[3]);
        }
    }
}

// ---- kernel 2: grouped tile sweep — A resident, B streamed ----
__global__ __launch_bounds__(256, 1)
void dcor_mma_kernel() {
    // decode group -> (bi, bj0)
    int g = blockIdx.x, bi = 0;
    for (;;) {
        const int ng = (NB - bi + GRP - 1) >> 2;
        if (g < ng) break;
        g -= ng; bi++;
    }
    const int bj0 = bi + g * GRP;
    const int ntiles = min(GRP, NB - bj0);

    extern __shared__ float sm[];
    const uint32_t smb = smem_u32(sm);
    float* NIX = sm + OFF_NIX;
    float* NIY = sm + OFF_NIY;
    float* NJX = sm + OFF_NJX;
    float* NJY = sm + OFF_NJY;
    float* COLPA = sm + OFF_COLPA;
    float* COLPB = sm + OFF_COLPB;
    float* ROWPA = sm + OFF_ROWPA;
    float* ROWPB = sm + OFF_ROWPB;

    const int tid = threadIdx.x, warp = tid >> 5, lane = tid & 31;
    const int I = bi * TILE;
    const int mwarp = warp & 3, nhalf = warp >> 2;
    const unsigned FULL = 0xffffffffu;

    issue_A(smb, I, tid);
    issue_B(smb, bj0 * TILE, 0, tid);
    CP_COMMIT();
    if (tid < 128) { NIX[tid] = g_norm_x[I + tid]; NIY[tid] = g_norm_y[I + tid]; }

    double s_aa = 0.0, s_bb = 0.0, s_ab = 0.0;
    float rowpa[2][2] = {{0.f, 0.f}, {0.f, 0.f}};
    float rowpb[2][2] = {{0.f, 0.f}, {0.f, 0.f}};

    for (int tt = 0; tt < ntiles; tt++) {
        const int bj = bj0 + tt, J = bj * TILE;
        const bool diag = (bj == bi);

        CP_WAIT(0);
        __syncthreads();                 // buf[tt&1] + (tt==0: A, NI) ready; COLP free
        if (tid < 128) { NJX[tid] = g_norm_x[J + tid]; NJY[tid] = g_norm_y[J + tid]; }
        if (tt + 1 < ntiles) {
            issue_B(smb, (bj + 1) * TILE, (tt + 1) & 1, tid);
            CP_COMMIT();
        }

        const uint32_t bBase = (uint32_t)(OFF_BUF + (tt & 1) * BUF_BYTES);
        float acc_x[2][8][4], acc_y[2][8][4];
#pragma unroll
        for (int mt = 0; mt < 2; mt++)
#pragma unroll
            for (int nt = 0; nt < 8; nt++)
#pragma unroll
                for (int q = 0; q < 4; q++) { acc_x[mt][nt][q] = 0.f; acc_y[mt][nt][q] = 0.f; }

        mma_mat(smb, OFF_AX, bBase,             acc_x, mwarp, nhalf, lane);
        mma_mat(smb, OFF_AY, bBase + ARR_BYTES, acc_y, mwarp, nhalf, lane);
        __syncthreads();                 // NJ visible to all for epilogue

        // ---- per-tile epilogue ----
        float njx[8][2], njy[8][2];
#pragma unroll
        for (int nt = 0; nt < 8; nt++) {
            const int col = nhalf * 64 + nt * 8 + (lane & 3) * 2;
            njx[nt][0] = NJX[col]; njx[nt][1] = NJX[col + 1];
            njy[nt][0] = NJY[col]; njy[nt][1] = NJY[col + 1];
        }

        float ssa = 0.f, ssb = 0.f, sab = 0.f;
        float colpa[8][2], colpb[8][2];
#pragma unroll
        for (int nt = 0; nt < 8; nt++) {
            colpa[nt][0] = 0.f; colpa[nt][1] = 0.f;
            colpb[nt][0] = 0.f; colpb[nt][1] = 0.f;
        }

#pragma unroll
        for (int mt = 0; mt < 2; mt++) {
#pragma unroll
            for (int pr = 0; pr < 2; pr++) {
                const int row = mwarp * 32 + mt * 16 + pr * 8 + (lane >> 2);
                const float nIx = NIX[row];
                const float nIy = NIY[row];
#pragma unroll
                for (int nt = 0; nt < 8; nt++) {
                    const int col = nhalf * 64 + nt * 8 + (lane & 3) * 2;
                    float gx0 = acc_x[mt][nt][pr * 2 + 0];
                    float gx1 = acc_x[mt][nt][pr * 2 + 1];
                    float gy0 = acc_y[mt][nt][pr * 2 + 0];
                    float gy1 = acc_y[mt][nt][pr * 2 + 1];
                    float sqx0 = fmaf(-2.f, gx0, nIx + njx[nt][0]);
                    float sqx1 = fmaf(-2.f, gx1, nIx + njx[nt][1]);
                    float sqy0 = fmaf(-2.f, gy0, nIy + njy[nt][0]);
                    float sqy1 = fmaf(-2.f, gy1, nIy + njy[nt][1]);
                    float dx0 = (sqx0 > 0.f) ? sqx0 * rsqrtf(sqx0) : 0.f;
                    float dx1 = (sqx1 > 0.f) ? sqx1 * rsqrtf(sqx1) : 0.f;
                    float dy0 = (sqy0 > 0.f) ? sqy0 * rsqrtf(sqy0) : 0.f;
                    float dy1 = (sqy1 > 0.f) ? sqy1 * rsqrtf(sqy1) : 0.f;
                    if (diag) {
                        if (row == col)     { dx0 = 0.f; dy0 = 0.f; }
                        if (row == col + 1) { dx1 = 0.f; dy1 = 0.f; }
                    }
                    ssa = fmaf(dx0, dx0, ssa); ssa = fmaf(dx1, dx1, ssa);
                    ssb = fmaf(dy0, dy0, ssb); ssb = fmaf(dy1, dy1, ssb);
                    sab = fmaf(dx0, dy0, sab); sab = fmaf(dx1, dy1, sab);
                    rowpa[mt][pr] += dx0 + dx1;
                    rowpb[mt][pr] += dy0 + dy1;
                    colpa[nt][0] += dx0; colpa[nt][1] += dx1;
                    colpb[nt][0] += dy0; colpb[nt][1] += dy1;
                }
            }
        }
        const double w = diag ? 1.0 : 2.0;
        s_aa += w * (double)ssa;
        s_bb += w * (double)ssb;
        s_ab += w * (double)sab;

        // col sums (per tile): reduce over the 8 row-lanes
#pragma unroll
        for (int nt = 0; nt < 8; nt++)
#pragma unroll
            for (int c2 = 0; c2 < 2; c2++) {
                float va = colpa[nt][c2], vb = colpb[nt][c2];
                va += __shfl_down_sync(FULL, va, 16);
                va += __shfl_down_sync(FULL, va, 8);
                va += __shfl_down_sync(FULL, va, 4);
                vb += __shfl_down_sync(FULL, vb, 16);
                vb += __shfl_down_sync(FULL, vb, 8);
                vb += __shfl_down_sync(FULL, vb, 4);
                colpa[nt][c2] = va; colpb[nt][c2] = vb;
            }
        if (lane < 4) {
#pragma unroll
            for (int nt = 0; nt < 8; nt++) {
                const int col = nhalf * 64 + nt * 8 + lane * 2;
                COLPA[mwarp * 128 + col]     = colpa[nt][0];
                COLPA[mwarp * 128 + col + 1] = colpa[nt][1];
                COLPB[mwarp * 128 + col]     = colpb[nt][0];
                COLPB[mwarp * 128 + col + 1] = colpb[nt][1];
            }
        }
        __syncthreads();
        if (!diag && tid < 128) {
            float csa = COLPA[tid] + COLPA[128 + tid] + COLPA[256 + tid] + COLPA[384 + tid];
            float csb = COLPB[tid] + COLPB[128 + tid] + COLPB[256 + tid] + COLPB[384 + tid];
            atomicAdd(&g_rs_a[J + tid], (double)csa);
            atomicAdd(&g_rs_b[J + tid], (double)csb);
        }
        // next iteration's top __syncthreads orders COLP reads before rewrite
    }

    // ---- group row sums (accumulated over all tiles) ----
#pragma unroll
    for (int mt = 0; mt < 2; mt++)
#pragma unroll
        for (int pr = 0; pr < 2; pr++) {
            float va = rowpa[mt][pr], vb = rowpb[mt][pr];
            va += __shfl_down_sync(FULL, va, 1);
            va += __shfl_down_sync(FULL, va, 2);
            rowpa[mt][pr] = va;
            vb += __shfl_down_sync(FULL, vb, 1);
            vb += __shfl_down_sync(FULL, vb, 2);
            rowpb[mt][pr] = vb;
        }
    __syncthreads();     // last tile's COLP reads done before ROWP write
    if ((lane & 3) == 0) {
#pragma unroll
        for (int mt = 0; mt < 2; mt++)
#pragma unroll
            for (int pr = 0; pr < 2; pr++) {
                const int row = mwarp * 32 + mt * 16 + pr * 8 + (lane >> 2);
                ROWPA[nhalf * 128 + row] = rowpa[mt][pr];
                ROWPB[nhalf * 128 + row] = rowpb[mt][pr];
            }
    }
    __syncthreads();
    if (tid < 128) {
        float rsa = ROWPA[tid] + ROWPA[128 + tid];
        float rsb = ROWPB[tid] + ROWPB[128 + tid];
        atomicAdd(&g_rs_a[I + tid], (double)rsa);
        atomicAdd(&g_rs_b[I + tid], (double)rsb);
    }

    // ---- block scalar reduction ----
#pragma unroll
    for (int o = 16; o; o >>= 1) {
        s_aa += __shfl_down_sync(FULL, s_aa, o);
        s_bb += __shfl_down_sync(FULL, s_bb, o);
        s_ab += __shfl_down_sync(FULL, s_ab, o);
    }
    __shared__ double redS[3][8];
    if (lane == 0) { redS[0][warp] = s_aa; redS[1][warp] = s_bb; redS[2][warp] = s_ab; }
    __syncthreads();
    if (tid == 0) {
        double a = 0, b = 0, c = 0;
#pragma unroll
        for (int k = 0; k < 8; k++) { a += redS[0][k]; b += redS[1][k]; c += redS[2][k]; }
        atomicAdd(&g_S[0], a);
        atomicAdd(&g_S[1], b);
        atomicAdd(&g_S[2], c);
    }
}

// ---- kernel 3: combine + final scalar ----
__global__ void finalize_kernel(float* __restrict__ out) {
    int tid = threadIdx.x;
    double dAB = 0, dAA = 0, dBB = 0, Ta = 0, Tb = 0;
    for (int i = tid; i < NPTS; i += 256) {
        double a = g_rs_a[i], b = g_rs_b[i];
        dAB += a * b; dAA += a * a; dBB += b * b; Ta += a; Tb += b;
    }
    const unsigned FULL = 0xffffffffu;
#pragma unroll
    for (int o = 16; o; o >>= 1) {
        dAB += __shfl_down_sync(FULL, dAB, o);
        dAA += __shfl_down_sync(FULL, dAA, o);
        dBB += __shfl_down_sync(FULL, dBB, o);
        Ta  += __shfl_down_sync(FULL, Ta,  o);
        Tb  += __shfl_down_sync(FULL, Tb,  o);
    }
    __shared__ double red[5][8];
    int wid = tid >> 5, lane = tid & 31;
    if (lane == 0) {
        red[0][wid] = dAB; red[1][wid] = dAA; red[2][wid] = dBB;
        red[3][wid] = Ta;  red[4][wid] = Tb;
    }
    __syncthreads();
    if (tid == 0) {
        double sAB = 0, sAA = 0, sBB = 0, ta = 0, tb = 0;
#pragma unroll
        for (int k = 0; k < 8; k++) {
            sAB += red[0][k]; sAA += red[1][k]; sBB += red[2][k];
            ta  += red[3][k]; tb  += red[4][k];
        }
        const double n = (double)NPTS;
        const double inv_n2 = 1.0 / (n * n);
        double xy = (g_S[2] - (2.0 / n) * sAB + ta * tb * inv_n2) * inv_n2;
        double xx = (g_S[0] - (2.0 / n) * sAA + ta * ta * inv_n2) * inv_n2;
        double yy = (g_S[1] - (2.0 / n) * sBB + tb * tb * inv_n2) * inv_n2;
        xy = fmax(xy, 0.0); xx = fmax(xx, 0.0); yy = fmax(yy, 0.0);
        double dcor = -sqrt(xy) / sqrt(sqrt(xx) * sqrt(yy));
        out[0] = (float)dcor;
    }
}

extern "C" void kernel_launch(void* const* d_in, const int* in_sizes, int n_in,
                              void* d_out, int out_size) {
    (void)in_sizes; (void)n_in; (void)out_size;
    const float* x = (const float*)d_in[0];
    const float* y = (const float*)d_in[1];
    float* out = (float*)d_out;

    cudaFuncSetAttribute(dcor_mma_kernel,
                         cudaFuncAttributeMaxDynamicSharedMemorySize, SMEM_BYTES);

    prep_kernel<<<NPTS / 8, 256>>>(x, y);
    dcor_mma_kernel<<<NGROUPS, 256, SMEM_BYTES>>>();
    finalize_kernel<<<1, 256>>>(out);
}